// round 7
// baseline (speedup 1.0000x reference)
#include <cuda_runtime.h>
#include <math.h>
#include <stdint.h>

#define BATCH 2
#define SEQ   2048
#define DM    1024
#define NHEAD 16
#define HS    64
#define FQ    256
#define BN3   3072   /* 3*NHEAD*HS */

// ---------------- scratch (device globals; no allocations allowed) ----------
__device__ float g_Q[BATCH*NHEAD*SEQ*HS];
__device__ float g_K[BATCH*NHEAD*SEQ*HS];
__device__ float g_V[BATCH*NHEAD*SEQ*HS];
__device__ float g_emb[NHEAD*SEQ*HS];
__device__ float g_O[BATCH*SEQ*NHEAD*HS];

// ---------------- tf32 mma helpers ------------------------------------------
__device__ __forceinline__ uint32_t f2t(float x) {
    uint32_t r; asm("cvt.rna.tf32.f32 %0, %1;" : "=r"(r) : "f"(x)); return r;
}
__device__ __forceinline__ void mma8(float c[4], const uint32_t a[4], const uint32_t b[2]) {
    asm volatile(
      "mma.sync.aligned.m16n8k8.row.col.f32.tf32.tf32.f32 "
      "{%0,%1,%2,%3}, {%4,%5,%6,%7}, {%8,%9}, {%0,%1,%2,%3};"
      : "+f"(c[0]), "+f"(c[1]), "+f"(c[2]), "+f"(c[3])
      : "r"(a[0]), "r"(a[1]), "r"(a[2]), "r"(a[3]), "r"(b[0]), "r"(b[1]));
}

// ---------------- 1) QKV projection: (4096x1024) @ (1024x3072), tf32 mma ----
// K-tile depth 32: half the barrier count of the k=16 version.
__global__ __launch_bounds__(256) void qkv_kernel(
    const float* __restrict__ inp, const float* __restrict__ w,
    const float* __restrict__ qb)
{
    __shared__ uint32_t sA[128][36];    // [m][k], stride 36 (==4 mod 32): conflict-free
    __shared__ uint32_t sB[32][136];    // [k][n], stride 136 (==8 mod 32): conflict-free
    const int tid = threadIdx.x, lane = tid & 31, wid = tid >> 5;
    const int g = lane >> 2, tg = lane & 3;
    const int warpN = wid & 1, warpM = wid >> 1;
    const int m0 = blockIdx.y * 128, n0 = blockIdx.x * 128;

    float acc[2][8][4] = {};
    for (int k0 = 0; k0 < DM; k0 += 32) {
        #pragma unroll
        for (int t = 0; t < 4; t++) {
            int e = tid + t * 256;
            int r = e >> 3, c = (e & 7) * 4;
            float4 v = *(const float4*)&inp[(size_t)(m0 + r) * DM + k0 + c];
            sA[r][c] = f2t(v.x); sA[r][c+1] = f2t(v.y);
            sA[r][c+2] = f2t(v.z); sA[r][c+3] = f2t(v.w);
            int rb = e >> 5, cb = (e & 31) * 4;
            float4 u = *(const float4*)&w[(size_t)(k0 + rb) * BN3 + n0 + cb];
            sB[rb][cb] = f2t(u.x); sB[rb][cb+1] = f2t(u.y);
            sB[rb][cb+2] = f2t(u.z); sB[rb][cb+3] = f2t(u.w);
        }
        __syncthreads();
        #pragma unroll
        for (int ks = 0; ks < 32; ks += 8) {
            uint32_t af[2][4];
            #pragma unroll
            for (int i = 0; i < 2; i++) {
                int mr = warpM * 32 + i * 16;
                af[i][0] = sA[mr + g    ][ks + tg    ];
                af[i][1] = sA[mr + g + 8][ks + tg    ];
                af[i][2] = sA[mr + g    ][ks + tg + 4];
                af[i][3] = sA[mr + g + 8][ks + tg + 4];
            }
            #pragma unroll
            for (int j = 0; j < 8; j++) {
                int nc = warpN * 64 + j * 8 + g;
                uint32_t bf[2] = { sB[ks + tg][nc], sB[ks + tg + 4][nc] };
                #pragma unroll
                for (int i = 0; i < 2; i++) mma8(acc[i][j], af[i], bf);
            }
        }
        __syncthreads();
    }

    const float qscale = powf(3.0f * DM * NHEAD * HS, -0.25f);
    #pragma unroll
    for (int i = 0; i < 2; i++) {
        #pragma unroll
        for (int j = 0; j < 8; j++) {
            #pragma unroll
            for (int cr = 0; cr < 4; cr++) {
                int m = m0 + warpM * 32 + i * 16 + g + (cr >> 1) * 8;
                int c = n0 + warpN * 64 + j * 8 + tg * 2 + (cr & 1);
                int b = m >> 11, s = m & (SEQ - 1);
                int A = c >> 10, n = (c >> 6) & 15, h = c & 63;
                float v = acc[i][j][cr] * qscale;
                size_t dst = ((size_t)(b * NHEAD + n) * SEQ + s) * HS + h;
                if (A == 0)      g_Q[dst] = v + qb[n * HS + h];
                else if (A == 1) g_K[dst] = v;
                else             g_V[dst] = v;
            }
        }
    }
}

// ---------------- 2) relative-position embedding table ----------------------
__global__ __launch_bounds__(256) void emb_kernel(const float* __restrict__ pos)
{
    __shared__ float ssin[FQ];
    const int s = blockIdx.x;
    const int tid = threadIdx.x;
    {
        int f = tid;
        double inv = pow(10000.0, -(double)((f >> 1) * 2) / (double)FQ);
        double ang = (double)s * inv;
        double v = (f & 1) ? cos(ang) : sin(ang);
        ssin[f] = (float)(1.4142135623730951 * v);
    }
    __syncthreads();

    int c4 = tid * 4;
    float a0 = 0.f, a1 = 0.f, a2 = 0.f, a3 = 0.f;
    for (int f = 0; f < FQ; f++) {
        float4 p = *reinterpret_cast<const float4*>(&pos[(size_t)f * (NHEAD * HS) + c4]);
        float sv = ssin[f];
        a0 += sv * p.x; a1 += sv * p.y; a2 += sv * p.z; a3 += sv * p.w;
    }
    const float pscale = 0.0625f;
    int n = c4 >> 6, h = c4 & 63;
    size_t base = ((size_t)n * SEQ + s) * HS + h;
    g_emb[base + 0] = a0 * pscale;
    g_emb[base + 1] = a1 * pscale;
    g_emb[base + 2] = a2 * pscale;
    g_emb[base + 3] = a3 * pscale;
}

// ---------------- 3) fused flash attention, 128-row q-tile, 512 threads -----
// SMEM word layout (dynamic):
//   sQ   [128][72] tf32, persistent                     @ 0      (9216)
//   sKE  [256][72] tf32 (K rows 0-63, E rows 64-255)    @ 9216   (18432)
//     stage2 alias: sC  [128][72] fp32/tf32 @ 9216
//                   sPB [128][68] fp32 banded @ 18432   (8704, fits in sKE tail)
//   sV   [64][72]  tf32                                 @ 27648  (4608)
//   m_s/l_s/rs [128] each                               @ 32256  (384)
extern __shared__ uint32_t smw[];
__global__ __launch_bounds__(512, 1) void attn_kernel()
{
    const int qt = (SEQ / 128 - 1) - blockIdx.x;   // longest blocks first
    const int bn = blockIdx.y;
    const int q0 = qt * 128;

    uint32_t* sQ  = smw;
    uint32_t* sKE = smw + 9216;
    float*    sC  = (float*)(smw + 9216);
    uint32_t* sCu = smw + 9216;
    float*    sPB = (float*)(smw + 18432);
    uint32_t* sV  = smw + 27648;
    float*    m_s = (float*)(smw + 32256);
    float*    l_s = m_s + 128;
    float*    rs  = m_s + 256;

    const float* Qg = g_Q + (size_t)bn * SEQ * HS;
    const float* Kg = g_K + (size_t)bn * SEQ * HS;
    const float* Vg = g_V + (size_t)bn * SEQ * HS;
    const int hd = bn & (NHEAD - 1);
    const float* Eg = g_emb + (size_t)hd * SEQ * HS;

    const int tid = threadIdx.x, lane = tid & 31, wid = tid >> 5;
    const int g = lane >> 2, tg = lane & 3;
    // QK phase warp grid: 4 x 4 (warp tile 32x64 of 128x256)
    const int wMs = wid & 3, wNs = wid >> 2;
    // PV phase warp grid: 8 x 2 (warp tile 16x32 of 128x64)
    const int wMo = wid & 7, wNo = wid >> 3;
    // softmax mapping: 4 threads per row, 128 rows
    const int srow = tid >> 2, sq4 = tid & 3;

    // load Q tile (persistent) + init state
    #pragma unroll
    for (int t = 0; t < 4; t++) {
        int e = tid + t * 512;
        int r = e >> 4, c = (e & 15) * 4;
        float4 v = *(const float4*)&Qg[(size_t)(q0 + r) * HS + c];
        sQ[r * 72 + c] = f2t(v.x); sQ[r * 72 + c + 1] = f2t(v.y);
        sQ[r * 72 + c + 2] = f2t(v.z); sQ[r * 72 + c + 3] = f2t(v.w);
    }
    if (tid < 128) { m_s[tid] = -1e30f; l_s[tid] = 0.f; }

    float acc_o[4][4] = {};
    const int ktmax = 2 * qt + 1;

    for (int kt = 0; kt <= ktmax; kt++) {
        const int k0 = kt * 64;
        int dlo = q0 - k0 - 63; if (dlo < 0) dlo = 0;
        const int base_off = q0 - k0 - 63 - dlo;   // band base = base_off + row

        __syncthreads();   // prior iteration's PV reads of sC/sV complete

        // ---- load K (rows 0-63) + E window (rows 64-255) ----
        #pragma unroll
        for (int t = 0; t < 8; t++) {
            int e = tid + t * 512;
            int r = e >> 4, c = (e & 15) * 4;
            float4 v;
            if (r < 64) {
                v = *(const float4*)&Kg[(size_t)(k0 + r) * HS + c];
            } else {
                int d = dlo + r - 64;
                if (d < SEQ) v = *(const float4*)&Eg[(size_t)d * HS + c];
                else         v = make_float4(0.f, 0.f, 0.f, 0.f);
            }
            sKE[r * 72 + c] = f2t(v.x); sKE[r * 72 + c + 1] = f2t(v.y);
            sKE[r * 72 + c + 2] = f2t(v.z); sKE[r * 72 + c + 3] = f2t(v.w);
        }
        // ---- load V (64 x 64) ----
        #pragma unroll
        for (int t = 0; t < 2; t++) {
            int e = tid + t * 512;
            int r = e >> 4, c = (e & 15) * 4;
            float4 u = *(const float4*)&Vg[(size_t)(k0 + r) * HS + c];
            sV[r * 72 + c] = f2t(u.x); sV[r * 72 + c + 1] = f2t(u.y);
            sV[r * 72 + c + 2] = f2t(u.z); sV[r * 72 + c + 3] = f2t(u.w);
        }
        __syncthreads();

        // ---- fused QK^T / Q@E^T MMA: 128 x 256 ----
        float acc_s[2][8][4] = {};
        #pragma unroll
        for (int ks = 0; ks < HS; ks += 8) {
            uint32_t af[2][4];
            #pragma unroll
            for (int i = 0; i < 2; i++) {
                int mr = wMs * 32 + i * 16;
                af[i][0] = sQ[(mr + g    ) * 72 + ks + tg    ];
                af[i][1] = sQ[(mr + g + 8) * 72 + ks + tg    ];
                af[i][2] = sQ[(mr + g    ) * 72 + ks + tg + 4];
                af[i][3] = sQ[(mr + g + 8) * 72 + ks + tg + 4];
            }
            #pragma unroll
            for (int j = 0; j < 8; j++) {
                int nc = wNs * 64 + j * 8 + g;
                uint32_t bf[2] = { sKE[nc * 72 + ks + tg], sKE[nc * 72 + ks + tg + 4] };
                #pragma unroll
                for (int i = 0; i < 2; i++) mma8(acc_s[i][j], af[i], bf);
            }
        }
        __syncthreads();   // all sKE reads done -> reuse region as sC/sPB

        // ---- scatter scores: content -> sC, positional -> banded sPB ----
        #pragma unroll
        for (int i = 0; i < 2; i++) {
            #pragma unroll
            for (int j = 0; j < 8; j++) {
                #pragma unroll
                for (int cr = 0; cr < 4; cr++) {
                    int row = wMs * 32 + i * 16 + g + (cr >> 1) * 8;
                    int col = wNs * 64 + j * 8 + tg * 2 + (cr & 1);
                    float v = acc_s[i][j][cr];
                    if (col < 64) {
                        sC[row * 72 + col] = v;
                    } else {
                        int b = (col - 64) - (base_off + row);
                        if ((unsigned)b < 64u) sPB[row * 68 + b] = v;
                    }
                }
            }
        }
        __syncthreads();

        // ---- gather + online softmax (4 threads per row, 16 cols each) ----
        {
            const int q = q0 + srow;
            const float m_old = m_s[srow];
            float sv[16];
            float tmax = -1e30f;
            #pragma unroll
            for (int i = 0; i < 16; i++) {
                int c = sq4 * 16 + i;
                int k = k0 + c;
                float x;
                if (k > q) x = -1e30f;
                else x = (sC[srow * 72 + c] + sPB[srow * 68 + (63 - c)]) * 0.125f;
                sv[i] = x;
                tmax = fmaxf(tmax, x);
            }
            tmax = fmaxf(tmax, __shfl_xor_sync(0xffffffffu, tmax, 1));
            tmax = fmaxf(tmax, __shfl_xor_sync(0xffffffffu, tmax, 2));
            const float m_new = fmaxf(m_old, tmax);
            float sum = 0.f;
            #pragma unroll
            for (int i = 0; i < 16; i++) {
                float p = __expf(sv[i] - m_new);
                sum += p;
                sC[srow * 72 + sq4 * 16 + i] = __uint_as_float(f2t(p));
            }
            sum += __shfl_xor_sync(0xffffffffu, sum, 1);
            sum += __shfl_xor_sync(0xffffffffu, sum, 2);
            if (sq4 == 0) {
                float sc = __expf(m_old - m_new);
                rs[srow]  = sc;
                m_s[srow] = m_new;
                l_s[srow] = l_s[srow] * sc + sum;
            }
        }
        __syncthreads();

        // ---- rescale O accumulator, then P @ V ----
        {
            const float s0 = rs[wMo * 16 + g];
            const float s1 = rs[wMo * 16 + g + 8];
            #pragma unroll
            for (int j = 0; j < 4; j++) {
                acc_o[j][0] *= s0; acc_o[j][1] *= s0;
                acc_o[j][2] *= s1; acc_o[j][3] *= s1;
            }
            #pragma unroll
            for (int ks = 0; ks < 64; ks += 8) {
                uint32_t af[4];
                int mr = wMo * 16;
                af[0] = sCu[(mr + g    ) * 72 + ks + tg    ];
                af[1] = sCu[(mr + g + 8) * 72 + ks + tg    ];
                af[2] = sCu[(mr + g    ) * 72 + ks + tg + 4];
                af[3] = sCu[(mr + g + 8) * 72 + ks + tg + 4];
                #pragma unroll
                for (int j = 0; j < 4; j++) {
                    int nc = wNo * 32 + j * 8 + g;
                    uint32_t bf[2] = { sV[(ks + tg) * 72 + nc], sV[(ks + tg + 4) * 72 + nc] };
                    mma8(acc_o[j], af, bf);
                }
            }
        }
    }

    // ---- epilogue: divide by l, store ----
    const int b = bn >> 4, n = bn & 15;
    const float inv0 = 1.f / l_s[wMo * 16 + g];
    const float inv1 = 1.f / l_s[wMo * 16 + g + 8];
    #pragma unroll
    for (int j = 0; j < 4; j++) {
        #pragma unroll
        for (int cr = 0; cr < 4; cr++) {
            int q = q0 + wMo * 16 + g + (cr >> 1) * 8;
            int h = wNo * 32 + j * 8 + tg * 2 + (cr & 1);
            g_O[(((size_t)b * SEQ + q) * NHEAD + n) * HS + h] =
                acc_o[j][cr] * ((cr >> 1) ? inv1 : inv0);
        }
    }
}

// ---------------- 4) out = O @ (out_kernel * scale) + bias, tf32 mma ---------
__global__ __launch_bounds__(256) void proj_kernel(
    const float* __restrict__ wk, const float* __restrict__ bias,
    float* __restrict__ out)
{
    __shared__ uint32_t sA[128][36];
    __shared__ uint32_t sB[32][136];
    const int tid = threadIdx.x, lane = tid & 31, wid = tid >> 5;
    const int g = lane >> 2, tg = lane & 3;
    const int warpN = wid & 1, warpM = wid >> 1;
    const int m0 = blockIdx.y * 128, n0 = blockIdx.x * 128;

    float acc[2][8][4] = {};
    for (int k0 = 0; k0 < DM; k0 += 32) {
        #pragma unroll
        for (int t = 0; t < 4; t++) {
            int e = tid + t * 256;
            int r = e >> 3, c = (e & 7) * 4;
            float4 v = *(const float4*)&g_O[(size_t)(m0 + r) * DM + k0 + c];
            sA[r][c] = f2t(v.x); sA[r][c+1] = f2t(v.y);
            sA[r][c+2] = f2t(v.z); sA[r][c+3] = f2t(v.w);
            int rb = e >> 5, cb = (e & 31) * 4;
            float4 u = *(const float4*)&wk[(size_t)(k0 + rb) * DM + n0 + cb];
            sB[rb][cb] = f2t(u.x); sB[rb][cb+1] = f2t(u.y);
            sB[rb][cb+2] = f2t(u.z); sB[rb][cb+3] = f2t(u.w);
        }
        __syncthreads();
        #pragma unroll
        for (int ks = 0; ks < 32; ks += 8) {
            uint32_t af[2][4];
            #pragma unroll
            for (int i = 0; i < 2; i++) {
                int mr = warpM * 32 + i * 16;
                af[i][0] = sA[mr + g    ][ks + tg    ];
                af[i][1] = sA[mr + g + 8][ks + tg    ];
                af[i][2] = sA[mr + g    ][ks + tg + 4];
                af[i][3] = sA[mr + g + 8][ks + tg + 4];
            }
            #pragma unroll
            for (int j = 0; j < 8; j++) {
                int nc = warpN * 64 + j * 8 + g;
                uint32_t bf[2] = { sB[ks + tg][nc], sB[ks + tg + 4][nc] };
                #pragma unroll
                for (int i = 0; i < 2; i++) mma8(acc[i][j], af[i], bf);
            }
        }
        __syncthreads();
    }

    const float okscale = 0.03125f;   // (1024*1024)^-0.25
    #pragma unroll
    for (int i = 0; i < 2; i++) {
        #pragma unroll
        for (int j = 0; j < 8; j++) {
            #pragma unroll
            for (int cr = 0; cr < 4; cr++) {
                int m = m0 + warpM * 32 + i * 16 + g + (cr >> 1) * 8;
                int c = n0 + warpN * 64 + j * 8 + tg * 2 + (cr & 1);
                out[(size_t)m * DM + c] = acc[i][j][cr] * okscale + bias[c];
            }
        }
    }
}

// ---------------- launcher ---------------------------------------------------
extern "C" void kernel_launch(void* const* d_in, const int* in_sizes, int n_in,
                              void* d_out, int out_size)
{
    const float* inp = (const float*)d_in[0];   // (2, 2048, 1024)
    const float* qkv = (const float*)d_in[1];   // (1024, 3, 16, 64)
    const float* qb  = (const float*)d_in[2];   // (16, 64)
    const float* pos = (const float*)d_in[3];   // (256, 16, 64)
    const float* wk  = (const float*)d_in[4];   // (1024, 1024)
    const float* ob  = (const float*)d_in[5];   // (1024,)
    float* out = (float*)d_out;                 // (2, 2048, 1024)

    const int AT_SMEM = 32640 * 4;   // 130560 B
    cudaFuncSetAttribute(attn_kernel,
                         cudaFuncAttributeMaxDynamicSharedMemorySize, AT_SMEM);

    qkv_kernel<<<dim3(BN3 / 128, (BATCH * SEQ) / 128), 256>>>(inp, qkv, qb);
    emb_kernel<<<SEQ, 256>>>(pos);
    attn_kernel<<<dim3(SEQ / 128, BATCH * NHEAD), 512, AT_SMEM>>>();
    proj_kernel<<<dim3(DM / 128, (BATCH * SEQ) / 128), 256>>>(wk, ob, out);
}

// round 9
// speedup vs baseline: 1.2299x; 1.2299x over previous
#include <cuda_runtime.h>
#include <math.h>
#include <stdint.h>

#define BATCH 2
#define SEQ   2048
#define SEQE  (SEQ + 64)   /* emb rows padded with 64 zero rows */
#define DM    1024
#define NHEAD 16
#define HS    64
#define FQ    256
#define BN3   3072   /* 3*NHEAD*HS */

// ---------------- scratch (device globals; no allocations allowed) ----------
// g_Q/g_K/g_V/g_emb hold tf32-rounded bit patterns (stored as float bits).
__device__ float g_Q[BATCH*NHEAD*SEQ*HS];
__device__ float g_K[BATCH*NHEAD*SEQ*HS];
__device__ float g_V[BATCH*NHEAD*SEQ*HS];
__device__ float g_emb[NHEAD*SEQE*HS];     // rows [SEQ, SEQE) stay zero
__device__ float g_O[BATCH*SEQ*NHEAD*HS];

// ---------------- tf32 mma helpers ------------------------------------------
__device__ __forceinline__ uint32_t f2t(float x) {
    uint32_t r; asm("cvt.rna.tf32.f32 %0, %1;" : "=r"(r) : "f"(x)); return r;
}
__device__ __forceinline__ void mma8(float c[4], const uint32_t a[4], const uint32_t b[2]) {
    asm volatile(
      "mma.sync.aligned.m16n8k8.row.col.f32.tf32.tf32.f32 "
      "{%0,%1,%2,%3}, {%4,%5,%6,%7}, {%8,%9}, {%0,%1,%2,%3};"
      : "+f"(c[0]), "+f"(c[1]), "+f"(c[2]), "+f"(c[3])
      : "r"(a[0]), "r"(a[1]), "r"(a[2]), "r"(a[3]), "r"(b[0]), "r"(b[1]));
}
__device__ __forceinline__ void cpa16(uint32_t dst, const void* src) {
    asm volatile("cp.async.cg.shared.global [%0], [%1], 16;" :: "r"(dst), "l"(src));
}
__device__ __forceinline__ void cpa_commit() {
    asm volatile("cp.async.commit_group;");
}
__device__ __forceinline__ void cpa_wait0() {
    asm volatile("cp.async.wait_group 0;");
}

// ---------------- 1) QKV projection: (4096x1024) @ (1024x3072), tf32 mma ----
__global__ __launch_bounds__(256) void qkv_kernel(
    const float* __restrict__ inp, const float* __restrict__ w,
    const float* __restrict__ qb)
{
    __shared__ uint32_t sA[128][36];
    __shared__ uint32_t sB[32][136];
    const int tid = threadIdx.x, lane = tid & 31, wid = tid >> 5;
    const int g = lane >> 2, tg = lane & 3;
    const int warpN = wid & 1, warpM = wid >> 1;
    const int m0 = blockIdx.y * 128, n0 = blockIdx.x * 128;

    float acc[2][8][4] = {};
    for (int k0 = 0; k0 < DM; k0 += 32) {
        #pragma unroll
        for (int t = 0; t < 4; t++) {
            int e = tid + t * 256;
            int r = e >> 3, c = (e & 7) * 4;
            float4 v = *(const float4*)&inp[(size_t)(m0 + r) * DM + k0 + c];
            sA[r][c] = f2t(v.x); sA[r][c+1] = f2t(v.y);
            sA[r][c+2] = f2t(v.z); sA[r][c+3] = f2t(v.w);
            int rb = e >> 5, cb = (e & 31) * 4;
            float4 u = *(const float4*)&w[(size_t)(k0 + rb) * BN3 + n0 + cb];
            sB[rb][cb] = f2t(u.x); sB[rb][cb+1] = f2t(u.y);
            sB[rb][cb+2] = f2t(u.z); sB[rb][cb+3] = f2t(u.w);
        }
        __syncthreads();
        #pragma unroll
        for (int ks = 0; ks < 32; ks += 8) {
            uint32_t af[2][4];
            #pragma unroll
            for (int i = 0; i < 2; i++) {
                int mr = warpM * 32 + i * 16;
                af[i][0] = sA[mr + g    ][ks + tg    ];
                af[i][1] = sA[mr + g + 8][ks + tg    ];
                af[i][2] = sA[mr + g    ][ks + tg + 4];
                af[i][3] = sA[mr + g + 8][ks + tg + 4];
            }
            #pragma unroll
            for (int j = 0; j < 8; j++) {
                int nc = warpN * 64 + j * 8 + g;
                uint32_t bf[2] = { sB[ks + tg][nc], sB[ks + tg + 4][nc] };
                #pragma unroll
                for (int i = 0; i < 2; i++) mma8(acc[i][j], af[i], bf);
            }
        }
        __syncthreads();
    }

    const float qscale = powf(3.0f * DM * NHEAD * HS, -0.25f);
    #pragma unroll
    for (int i = 0; i < 2; i++) {
        #pragma unroll
        for (int j = 0; j < 8; j++) {
            #pragma unroll
            for (int cr = 0; cr < 4; cr++) {
                int m = m0 + warpM * 32 + i * 16 + g + (cr >> 1) * 8;
                int c = n0 + warpN * 64 + j * 8 + tg * 2 + (cr & 1);
                int b = m >> 11, s = m & (SEQ - 1);
                int A = c >> 10, n = (c >> 6) & 15, h = c & 63;
                float v = acc[i][j][cr] * qscale;
                size_t dst = ((size_t)(b * NHEAD + n) * SEQ + s) * HS + h;
                if (A == 0)      g_Q[dst] = __uint_as_float(f2t(v + qb[n * HS + h]));
                else if (A == 1) g_K[dst] = __uint_as_float(f2t(v));
                else             g_V[dst] = __uint_as_float(f2t(v));
            }
        }
    }
}

// ---------------- 2) relative-position embedding table (tf32 bits out) ------
__global__ __launch_bounds__(256) void emb_kernel(const float* __restrict__ pos)
{
    __shared__ float ssin[FQ];
    const int s = blockIdx.x;
    const int tid = threadIdx.x;
    {
        int f = tid;
        double inv = pow(10000.0, -(double)((f >> 1) * 2) / (double)FQ);
        double ang = (double)s * inv;
        double v = (f & 1) ? cos(ang) : sin(ang);
        ssin[f] = (float)(1.4142135623730951 * v);
    }
    __syncthreads();

    int c4 = tid * 4;
    float a0 = 0.f, a1 = 0.f, a2 = 0.f, a3 = 0.f;
    for (int f = 0; f < FQ; f++) {
        float4 p = *reinterpret_cast<const float4*>(&pos[(size_t)f * (NHEAD * HS) + c4]);
        float sv = ssin[f];
        a0 += sv * p.x; a1 += sv * p.y; a2 += sv * p.z; a3 += sv * p.w;
    }
    const float pscale = 0.0625f;
    int n = c4 >> 6, h = c4 & 63;
    size_t base = ((size_t)n * SEQE + s) * HS + h;
    g_emb[base + 0] = __uint_as_float(f2t(a0 * pscale));
    g_emb[base + 1] = __uint_as_float(f2t(a1 * pscale));
    g_emb[base + 2] = __uint_as_float(f2t(a2 * pscale));
    g_emb[base + 3] = __uint_as_float(f2t(a3 * pscale));
}

// ---------------- 3) fused flash attention, 64-row q-tile, cp.async KE ------
// SMEM word layout (dynamic), 27840 words = 111360 B (2 blocks/SM):
//   sQ   [64][72]  tf32, persistent                 @ 0
//   sKE  [192][72] tf32 (K rows 0-63, E rows 64-191)@ 4608
//     stage2 alias: sP [64][132] fp32 panel         @ 4608
//   sPr  [64][72]  scores->probs (separate!)        @ 18432
//   sV   [64][72]  tf32                             @ 23040
//   m_s/l_s/rs [64] each                            @ 27648
extern __shared__ uint32_t smw[];
__global__ __launch_bounds__(256, 2) void attn_kernel()
{
    const int qt = (SEQ / 64 - 1) - blockIdx.x;   // longest blocks first
    const int bn = blockIdx.y;
    const int q0 = qt * 64;

    uint32_t* sQ  = smw;
    uint32_t* sKE = smw + 4608;
    float*    sP  = (float*)(smw + 4608);
    uint32_t* sPr = smw + 18432;
    float*    sPrf= (float*)sPr;
    uint32_t* sV  = smw + 23040;
    float*    m_s = (float*)(smw + 27648);
    float*    l_s = m_s + 64;
    float*    rs  = m_s + 128;

    const float* Qg = g_Q + (size_t)bn * SEQ * HS;
    const float* Kg = g_K + (size_t)bn * SEQ * HS;
    const float* Vg = g_V + (size_t)bn * SEQ * HS;
    const int hd = bn & (NHEAD - 1);
    const float* Eg = g_emb + (size_t)hd * SEQE * HS;

    const uint32_t uKE = (uint32_t)__cvta_generic_to_shared(sKE);

    const int tid = threadIdx.x, lane = tid & 31, wid = tid >> 5;
    const int g = lane >> 2, tg = lane & 3;
    const int wMs = wid & 1, wNs = wid >> 1;   // QK: 2x4 grid, warp tile 32x48
    const int wMo = wid & 3, wNo = wid >> 2;   // PV: 4x2 grid, warp tile 16x32
    const int srow = tid >> 2, sq4 = tid & 3;  // softmax: 4 threads/row

    // load Q tile (raw tf32 bits) + init state
    #pragma unroll
    for (int t = 0; t < 4; t++) {
        int e = tid + t * 256;
        int r = e >> 4, c = (e & 15) * 4;
        *(uint4*)&sQ[r * 72 + c] = *(const uint4*)&Qg[(size_t)(q0 + r) * HS + c];
    }
    if (tid < 64) { m_s[tid] = -1e30f; l_s[tid] = 0.f; }

    // prologue: prefetch KE tile for kt=0
    {
        const int k0 = 0;
        int dlo = q0 - k0 - 63; if (dlo < 0) dlo = 0;
        #pragma unroll
        for (int t = 0; t < 12; t++) {
            int e = tid + t * 256;
            int r = e >> 4, c16 = e & 15;
            const float* src = (r < 64) ? &Kg[(size_t)(k0 + r) * HS + c16 * 4]
                                        : &Eg[(size_t)(dlo + r - 64) * HS + c16 * 4];
            cpa16(uKE + (r * 72 + c16 * 4) * 4, src);
        }
        cpa_commit();
    }

    float acc_o[4][4] = {};

    for (int kt = 0; kt <= qt; kt++) {
        const int k0 = kt * 64;
        int dlo = q0 - k0 - 63; if (dlo < 0) dlo = 0;

        __syncthreads();   // S0: prior iteration's PV reads of sPr/sV complete

        // ---- V load (raw 16B copies) ----
        #pragma unroll
        for (int t = 0; t < 4; t++) {
            int e = tid + t * 256;
            int r = e >> 4, c = (e & 15) * 4;
            *(uint4*)&sV[r * 72 + c] = *(const uint4*)&Vg[(size_t)(k0 + r) * HS + c];
        }
        cpa_wait0();       // KE tile for this kt has landed
        __syncthreads();   // S1

        // ---- fused QK^T / Q@E^T MMA: 64 x 192 ----
        float acc_s[2][6][4] = {};
        #pragma unroll
        for (int ks = 0; ks < HS; ks += 8) {
            uint32_t af[2][4];
            #pragma unroll
            for (int i = 0; i < 2; i++) {
                int mr = wMs * 32 + i * 16;
                af[i][0] = sQ[(mr + g    ) * 72 + ks + tg    ];
                af[i][1] = sQ[(mr + g + 8) * 72 + ks + tg    ];
                af[i][2] = sQ[(mr + g    ) * 72 + ks + tg + 4];
                af[i][3] = sQ[(mr + g + 8) * 72 + ks + tg + 4];
            }
            #pragma unroll
            for (int j = 0; j < 6; j++) {
                int nc = wNs * 48 + j * 8 + g;
                uint32_t bf[2] = { sKE[nc * 72 + ks + tg], sKE[nc * 72 + ks + tg + 4] };
                #pragma unroll
                for (int i = 0; i < 2; i++) mma8(acc_s[i][j], af[i], bf);
            }
        }
        __syncthreads();   // S2: all sKE reads done -> positional panel may alias

        // ---- scatter: content -> sPr (fp32), positional -> sP panel ----
        #pragma unroll
        for (int i = 0; i < 2; i++) {
            #pragma unroll
            for (int j = 0; j < 6; j++) {
                #pragma unroll
                for (int cr = 0; cr < 4; cr++) {
                    int row = wMs * 32 + i * 16 + g + (cr >> 1) * 8;
                    int col = wNs * 48 + j * 8 + tg * 2 + (cr & 1);
                    float v = acc_s[i][j][cr];
                    if (col < 64) sPrf[row * 72 + col] = v;
                    else          sP[row * 132 + (col - 64)] = v;
                }
            }
        }
        __syncthreads();   // S3

        // ---- gather + online softmax (4 threads per row, 16 cols each) ----
        {
            const int q = q0 + srow;
            const float m_old = m_s[srow];
            const bool diag = (kt == qt);
            float sv[16];
            float tmax = -1e30f;
            #pragma unroll
            for (int i = 0; i < 16; i++) {
                int c = sq4 * 16 + i;
                int k = k0 + c;
                float x;
                if (diag && k > q) x = -1e30f;
                else x = (sPrf[srow * 72 + c] + sP[srow * 132 + (q - k - dlo)]) * 0.125f;
                sv[i] = x;
                tmax = fmaxf(tmax, x);
            }
            tmax = fmaxf(tmax, __shfl_xor_sync(0xffffffffu, tmax, 1));
            tmax = fmaxf(tmax, __shfl_xor_sync(0xffffffffu, tmax, 2));
            const float m_new = fmaxf(m_old, tmax);
            float sum = 0.f;
            #pragma unroll
            for (int i = 0; i < 16; i++) {
                float p = __expf(sv[i] - m_new);
                sum += p;
                sPr[srow * 72 + sq4 * 16 + i] = f2t(p);
            }
            sum += __shfl_xor_sync(0xffffffffu, sum, 1);
            sum += __shfl_xor_sync(0xffffffffu, sum, 2);
            if (sq4 == 0) {
                float sc = __expf(m_old - m_new);
                rs[srow]  = sc;
                m_s[srow] = m_new;
                l_s[srow] = l_s[srow] * sc + sum;
            }
        }
        __syncthreads();   // S4

        // ---- prefetch next KE tile (overlaps PV MMA below) ----
        if (kt < qt) {
            const int k0n = k0 + 64;
            int dlon = q0 - k0n - 63; if (dlon < 0) dlon = 0;
            #pragma unroll
            for (int t = 0; t < 12; t++) {
                int e = tid + t * 256;
                int r = e >> 4, c16 = e & 15;
                const float* src = (r < 64) ? &Kg[(size_t)(k0n + r) * HS + c16 * 4]
                                            : &Eg[(size_t)(dlon + r - 64) * HS + c16 * 4];
                cpa16(uKE + (r * 72 + c16 * 4) * 4, src);
            }
            cpa_commit();
        }

        // ---- rescale O accumulator, then P @ V ----
        {
            const float s0 = rs[wMo * 16 + g];
            const float s1 = rs[wMo * 16 + g + 8];
            #pragma unroll
            for (int j = 0; j < 4; j++) {
                acc_o[j][0] *= s0; acc_o[j][1] *= s0;
                acc_o[j][2] *= s1; acc_o[j][3] *= s1;
            }
            #pragma unroll
            for (int ks = 0; ks < 64; ks += 8) {
                uint32_t af[4];
                int mr = wMo * 16;
                af[0] = sPr[(mr + g    ) * 72 + ks + tg    ];
                af[1] = sPr[(mr + g + 8) * 72 + ks + tg    ];
                af[2] = sPr[(mr + g    ) * 72 + ks + tg + 4];
                af[3] = sPr[(mr + g + 8) * 72 + ks + tg + 4];
                #pragma unroll
                for (int j = 0; j < 4; j++) {
                    int nc = wNo * 32 + j * 8 + g;
                    uint32_t bf[2] = { sV[(ks + tg) * 72 + nc], sV[(ks + tg + 4) * 72 + nc] };
                    mma8(acc_o[j], af, bf);
                }
            }
        }
    }

    // ---- epilogue: divide by l, store ----
    const int b = bn >> 4, n = bn & 15;
    const float inv0 = 1.f / l_s[wMo * 16 + g];
    const float inv1 = 1.f / l_s[wMo * 16 + g + 8];
    #pragma unroll
    for (int j = 0; j < 4; j++) {
        #pragma unroll
        for (int cr = 0; cr < 4; cr++) {
            int q = q0 + wMo * 16 + g + (cr >> 1) * 8;
            int h = wNo * 32 + j * 8 + tg * 2 + (cr & 1);
            g_O[(((size_t)b * SEQ + q) * NHEAD + n) * HS + h] =
                acc_o[j][cr] * ((cr >> 1) ? inv1 : inv0);
        }
    }
}

// ---------------- 4) out = O @ (out_kernel * scale) + bias, tf32 mma ---------
__global__ __launch_bounds__(256) void proj_kernel(
    const float* __restrict__ wk, const float* __restrict__ bias,
    float* __restrict__ out)
{
    __shared__ uint32_t sA[128][36];
    __shared__ uint32_t sB[32][136];
    const int tid = threadIdx.x, lane = tid & 31, wid = tid >> 5;
    const int g = lane >> 2, tg = lane & 3;
    const int warpN = wid & 1, warpM = wid >> 1;
    const int m0 = blockIdx.y * 128, n0 = blockIdx.x * 128;

    float acc[2][8][4] = {};
    for (int k0 = 0; k0 < DM; k0 += 32) {
        #pragma unroll
        for (int t = 0; t < 4; t++) {
            int e = tid + t * 256;
            int r = e >> 3, c = (e & 7) * 4;
            float4 v = *(const float4*)&g_O[(size_t)(m0 + r) * DM + k0 + c];
            sA[r][c] = f2t(v.x); sA[r][c+1] = f2t(v.y);
            sA[r][c+2] = f2t(v.z); sA[r][c+3] = f2t(v.w);
            int rb = e >> 5, cb = (e & 31) * 4;
            float4 u = *(const float4*)&wk[(size_t)(k0 + rb) * DM + n0 + cb];
            sB[rb][cb] = f2t(u.x); sB[rb][cb+1] = f2t(u.y);
            sB[rb][cb+2] = f2t(u.z); sB[rb][cb+3] = f2t(u.w);
        }
        __syncthreads();
        #pragma unroll
        for (int ks = 0; ks < 32; ks += 8) {
            uint32_t af[2][4];
            #pragma unroll
            for (int i = 0; i < 2; i++) {
                int mr = warpM * 32 + i * 16;
                af[i][0] = sA[mr + g    ][ks + tg    ];
                af[i][1] = sA[mr + g + 8][ks + tg    ];
                af[i][2] = sA[mr + g    ][ks + tg + 4];
                af[i][3] = sA[mr + g + 8][ks + tg + 4];
            }
            #pragma unroll
            for (int j = 0; j < 8; j++) {
                int nc = warpN * 64 + j * 8 + g;
                uint32_t bf[2] = { sB[ks + tg][nc], sB[ks + tg + 4][nc] };
                #pragma unroll
                for (int i = 0; i < 2; i++) mma8(acc[i][j], af[i], bf);
            }
        }
        __syncthreads();
    }

    const float okscale = 0.03125f;   // (1024*1024)^-0.25
    #pragma unroll
    for (int i = 0; i < 2; i++) {
        #pragma unroll
        for (int j = 0; j < 8; j++) {
            #pragma unroll
            for (int cr = 0; cr < 4; cr++) {
                int m = m0 + warpM * 32 + i * 16 + g + (cr >> 1) * 8;
                int c = n0 + warpN * 64 + j * 8 + tg * 2 + (cr & 1);
                out[(size_t)m * DM + c] = acc[i][j][cr] * okscale + bias[c];
            }
        }
    }
}

// ---------------- launcher ---------------------------------------------------
extern "C" void kernel_launch(void* const* d_in, const int* in_sizes, int n_in,
                              void* d_out, int out_size)
{
    const float* inp = (const float*)d_in[0];   // (2, 2048, 1024)
    const float* qkv = (const float*)d_in[1];   // (1024, 3, 16, 64)
    const float* qb  = (const float*)d_in[2];   // (16, 64)
    const float* pos = (const float*)d_in[3];   // (256, 16, 64)
    const float* wk  = (const float*)d_in[4];   // (1024, 1024)
    const float* ob  = (const float*)d_in[5];   // (1024,)
    float* out = (float*)d_out;                 // (2, 2048, 1024)

    const int AT_SMEM = 27840 * 4;   // 111360 B -> 2 blocks/SM
    cudaFuncSetAttribute(attn_kernel,
                         cudaFuncAttributeMaxDynamicSharedMemorySize, AT_SMEM);

    qkv_kernel<<<dim3(BN3 / 128, (BATCH * SEQ) / 128), 256>>>(inp, qkv, qb);
    emb_kernel<<<SEQ, 256>>>(pos);
    attn_kernel<<<dim3(SEQ / 64, BATCH * NHEAD), 256, AT_SMEM>>>();
    proj_kernel<<<dim3(DM / 128, (BATCH * SEQ) / 128), 256>>>(wk, ob, out);
}

// round 10
// speedup vs baseline: 1.4724x; 1.1972x over previous
#include <cuda_runtime.h>
#include <cuda_fp16.h>
#include <math.h>
#include <stdint.h>

#define BATCH 2
#define SEQ   2048
#define SEQE  (SEQ + 64)   /* emb rows padded with 64 zero rows */
#define DM    1024
#define NHEAD 16
#define HS    64
#define FQ    256
#define BN3   3072   /* 3*NHEAD*HS */

// ---------------- scratch (device globals; no allocations allowed) ----------
__device__ __half g_Qh[BATCH*NHEAD*SEQ*HS];   // [bn][s][h]
__device__ __half g_Kh[BATCH*NHEAD*SEQ*HS];   // [bn][s][h]
__device__ __half g_Vh[BATCH*NHEAD*SEQ*HS];   // packed [bn][s/2][h][2]
__device__ __half g_embh[NHEAD*SEQE*HS];      // [n][d][h], rows [SEQ,SEQE) zero
__device__ float  g_O[BATCH*SEQ*NHEAD*HS];

// ---------------- mma helpers ------------------------------------------------
__device__ __forceinline__ uint32_t f2t(float x) {
    uint32_t r; asm("cvt.rna.tf32.f32 %0, %1;" : "=r"(r) : "f"(x)); return r;
}
__device__ __forceinline__ void mma8(float c[4], const uint32_t a[4], const uint32_t b[2]) {
    asm volatile(
      "mma.sync.aligned.m16n8k8.row.col.f32.tf32.tf32.f32 "
      "{%0,%1,%2,%3}, {%4,%5,%6,%7}, {%8,%9}, {%0,%1,%2,%3};"
      : "+f"(c[0]), "+f"(c[1]), "+f"(c[2]), "+f"(c[3])
      : "r"(a[0]), "r"(a[1]), "r"(a[2]), "r"(a[3]), "r"(b[0]), "r"(b[1]));
}
__device__ __forceinline__ void mma16(float c[4], const uint32_t a[4], const uint32_t b[2]) {
    asm volatile(
      "mma.sync.aligned.m16n8k16.row.col.f32.f16.f16.f32 "
      "{%0,%1,%2,%3}, {%4,%5,%6,%7}, {%8,%9}, {%0,%1,%2,%3};"
      : "+f"(c[0]), "+f"(c[1]), "+f"(c[2]), "+f"(c[3])
      : "r"(a[0]), "r"(a[1]), "r"(a[2]), "r"(a[3]), "r"(b[0]), "r"(b[1]));
}
__device__ __forceinline__ void cpa16(uint32_t dst, const void* src) {
    asm volatile("cp.async.cg.shared.global [%0], [%1], 16;" :: "r"(dst), "l"(src));
}
__device__ __forceinline__ void cpa_commit() {
    asm volatile("cp.async.commit_group;");
}
__device__ __forceinline__ void cpa_wait0() {
    asm volatile("cp.async.wait_group 0;");
}

// ---------------- 1) QKV projection: (4096x1024) @ (1024x3072), tf32 mma ----
__global__ __launch_bounds__(256) void qkv_kernel(
    const float* __restrict__ inp, const float* __restrict__ w,
    const float* __restrict__ qb)
{
    __shared__ uint32_t sA[128][36];
    __shared__ uint32_t sB[32][136];
    const int tid = threadIdx.x, lane = tid & 31, wid = tid >> 5;
    const int g = lane >> 2, tg = lane & 3;
    const int warpN = wid & 1, warpM = wid >> 1;
    const int m0 = blockIdx.y * 128, n0 = blockIdx.x * 128;

    float acc[2][8][4] = {};
    for (int k0 = 0; k0 < DM; k0 += 32) {
        #pragma unroll
        for (int t = 0; t < 4; t++) {
            int e = tid + t * 256;
            int r = e >> 3, c = (e & 7) * 4;
            float4 v = *(const float4*)&inp[(size_t)(m0 + r) * DM + k0 + c];
            sA[r][c] = f2t(v.x); sA[r][c+1] = f2t(v.y);
            sA[r][c+2] = f2t(v.z); sA[r][c+3] = f2t(v.w);
            int rb = e >> 5, cb = (e & 31) * 4;
            float4 u = *(const float4*)&w[(size_t)(k0 + rb) * BN3 + n0 + cb];
            sB[rb][cb] = f2t(u.x); sB[rb][cb+1] = f2t(u.y);
            sB[rb][cb+2] = f2t(u.z); sB[rb][cb+3] = f2t(u.w);
        }
        __syncthreads();
        #pragma unroll
        for (int ks = 0; ks < 32; ks += 8) {
            uint32_t af[2][4];
            #pragma unroll
            for (int i = 0; i < 2; i++) {
                int mr = warpM * 32 + i * 16;
                af[i][0] = sA[mr + g    ][ks + tg    ];
                af[i][1] = sA[mr + g + 8][ks + tg    ];
                af[i][2] = sA[mr + g    ][ks + tg + 4];
                af[i][3] = sA[mr + g + 8][ks + tg + 4];
            }
            #pragma unroll
            for (int j = 0; j < 8; j++) {
                int nc = warpN * 64 + j * 8 + g;
                uint32_t bf[2] = { sB[ks + tg][nc], sB[ks + tg + 4][nc] };
                #pragma unroll
                for (int i = 0; i < 2; i++) mma8(acc[i][j], af[i], bf);
            }
        }
        __syncthreads();
    }

    const float qscale = powf(3.0f * DM * NHEAD * HS, -0.25f);
    #pragma unroll
    for (int i = 0; i < 2; i++) {
        #pragma unroll
        for (int j = 0; j < 8; j++) {
            #pragma unroll
            for (int cr = 0; cr < 4; cr++) {
                int m = m0 + warpM * 32 + i * 16 + g + (cr >> 1) * 8;
                int c = n0 + warpN * 64 + j * 8 + tg * 2 + (cr & 1);
                int b = m >> 11, s = m & (SEQ - 1);
                int A = c >> 10, n = (c >> 6) & 15, h = c & 63;
                float v = acc[i][j][cr] * qscale;
                size_t bn = (size_t)(b * NHEAD + n);
                if (A == 0)
                    g_Qh[(bn * SEQ + s) * HS + h] = __float2half_rn(v + qb[n * HS + h]);
                else if (A == 1)
                    g_Kh[(bn * SEQ + s) * HS + h] = __float2half_rn(v);
                else
                    g_Vh[((bn * (SEQ/2) + (s >> 1)) * HS + h) * 2 + (s & 1)] = __float2half_rn(v);
            }
        }
    }
}

// ---------------- 2) relative-position embedding table (fp16 out) -----------
__global__ __launch_bounds__(256) void emb_kernel(const float* __restrict__ pos)
{
    __shared__ float ssin[FQ];
    const int s = blockIdx.x;
    const int tid = threadIdx.x;
    {
        int f = tid;
        double inv = pow(10000.0, -(double)((f >> 1) * 2) / (double)FQ);
        double ang = (double)s * inv;
        double v = (f & 1) ? cos(ang) : sin(ang);
        ssin[f] = (float)(1.4142135623730951 * v);
    }
    __syncthreads();

    int c4 = tid * 4;
    float a0 = 0.f, a1 = 0.f, a2 = 0.f, a3 = 0.f;
    for (int f = 0; f < FQ; f++) {
        float4 p = *reinterpret_cast<const float4*>(&pos[(size_t)f * (NHEAD * HS) + c4]);
        float sv = ssin[f];
        a0 += sv * p.x; a1 += sv * p.y; a2 += sv * p.z; a3 += sv * p.w;
    }
    const float pscale = 0.0625f;
    int n = c4 >> 6, h = c4 & 63;
    size_t base = ((size_t)n * SEQE + s) * HS + h;
    g_embh[base + 0] = __float2half_rn(a0 * pscale);
    g_embh[base + 1] = __float2half_rn(a1 * pscale);
    g_embh[base + 2] = __float2half_rn(a2 * pscale);
    g_embh[base + 3] = __float2half_rn(a3 * pscale);
}

// ---------------- 3) fused flash attention, fp16 mma (m16n8k16) -------------
// SMEM word layout (dynamic), 22592 words = 90368 B (2 blocks/SM):
//   sQh   [64][36]  h-pair words, persistent   @ 0
//   sKEh  [192][36] (K rows 0-63, E 64-191)    @ 2304
//   sCont [64][68]  fp32 content scores        @ 9216
//   sPB   [64][68]  fp32 banded pos panel      @ 13568
//   sPh   [64][36]  P fp16 k-pair words        @ 17920
//   sVh   [32][68]  V k-pair words             @ 20224
//   m_s/l_s/rs [64] each                       @ 22400
extern __shared__ uint32_t smw[];
__global__ __launch_bounds__(256, 2) void attn_kernel()
{
    const int qt = (SEQ / 64 - 1) - blockIdx.x;   // longest blocks first
    const int bn = blockIdx.y;
    const int q0 = qt * 64;

    uint32_t* sQh  = smw;
    uint32_t* sKEh = smw + 2304;
    float*    sCont= (float*)(smw + 9216);
    float*    sPB  = (float*)(smw + 13568);
    uint32_t* sPh  = smw + 17920;
    uint32_t* sVh  = smw + 20224;
    float*    m_s  = (float*)(smw + 22400);
    float*    l_s  = m_s + 64;
    float*    rs   = m_s + 128;

    const uint32_t* Qg = (const uint32_t*)g_Qh + (size_t)bn * SEQ * (HS/2);
    const __half*   Kg = g_Kh + (size_t)bn * SEQ * HS;
    const uint32_t* Vg = (const uint32_t*)g_Vh + (size_t)bn * (SEQ/2) * HS;
    const int hd = bn & (NHEAD - 1);
    const __half*   Eg = g_embh + (size_t)hd * SEQE * HS;

    const uint32_t uKE = (uint32_t)__cvta_generic_to_shared(sKEh);

    const int tid = threadIdx.x, lane = tid & 31, wid = tid >> 5;
    const int g = lane >> 2, tg = lane & 3;
    const int wMs = wid & 1, wNs = wid >> 1;   // QK: 2x4 grid, warp tile 32x48
    const int wMo = wid & 3, wNo = wid >> 2;   // PV: 4x2 grid, warp tile 16x32
    const int srow = tid >> 2, sq4 = tid & 3;  // softmax: 4 threads/row

    // load Q tile (h-pair words) + init state
    #pragma unroll
    for (int t = 0; t < 2; t++) {
        int e = tid + t * 256;
        int r = e >> 3, c = (e & 7) * 4;
        *(uint4*)&sQh[r * 36 + c] = *(const uint4*)&Qg[(size_t)(q0 + r) * (HS/2) + c];
    }
    if (tid < 64) { m_s[tid] = -1e30f; l_s[tid] = 0.f; }

    // prologue: prefetch KE tile for kt=0 (16B = 8 halves per chunk)
    {
        int dlo = q0 - 63; if (dlo < 0) dlo = 0;
        #pragma unroll
        for (int t = 0; t < 6; t++) {
            int e = tid + t * 256;
            int r = e >> 3, c8 = e & 7;
            const __half* src = (r < 64) ? Kg + (size_t)r * HS + c8 * 8
                                         : Eg + (size_t)(dlo + r - 64) * HS + c8 * 8;
            cpa16(uKE + (r * 36 + c8 * 4) * 4, src);
        }
        cpa_commit();
    }

    float acc_o[4][4] = {};

    for (int kt = 0; kt <= qt; kt++) {
        const int k0 = kt * 64;
        int dlo = q0 - k0 - 63; if (dlo < 0) dlo = 0;
        const int base_off = q0 - k0 - 63 - dlo;   // 0 except diag tile (-63)

        __syncthreads();   // S0: prior iteration's PV reads of sPh/sVh done

        // ---- V load (k-pair packed rows, 16B copies) ----
        #pragma unroll
        for (int t = 0; t < 2; t++) {
            int e = tid + t * 256;
            int r = e >> 4, c = (e & 15) * 4;
            *(uint4*)&sVh[r * 68 + c] = *(const uint4*)&Vg[(size_t)((k0 >> 1) + r) * HS + c];
        }
        cpa_wait0();       // KE tile for this kt has landed
        __syncthreads();   // S1

        // ---- fused QK^T / Q@E^T HMMA: 64 x 192, K=64 in 4 k16-steps ----
        float acc_s[2][6][4] = {};
        #pragma unroll
        for (int ks = 0; ks < 4; ks++) {
            uint32_t af[2][4];
            #pragma unroll
            for (int i = 0; i < 2; i++) {
                int mr = wMs * 32 + i * 16;
                af[i][0] = sQh[(mr + g    ) * 36 + ks * 8 + tg    ];
                af[i][1] = sQh[(mr + g + 8) * 36 + ks * 8 + tg    ];
                af[i][2] = sQh[(mr + g    ) * 36 + ks * 8 + tg + 4];
                af[i][3] = sQh[(mr + g + 8) * 36 + ks * 8 + tg + 4];
            }
            #pragma unroll
            for (int j = 0; j < 6; j++) {
                int nc = wNs * 48 + j * 8 + g;
                uint32_t bf[2] = { sKEh[nc * 36 + ks * 8 + tg],
                                   sKEh[nc * 36 + ks * 8 + tg + 4] };
                #pragma unroll
                for (int i = 0; i < 2; i++) mma16(acc_s[i][j], af[i], bf);
            }
        }
        // no barrier needed: sCont/sPB are not aliased with sKEh, and their
        // previous readers (softmax) finished before this iteration's S0.

        // ---- scatter: content -> sCont, positional -> banded sPB ----
        #pragma unroll
        for (int i = 0; i < 2; i++) {
            #pragma unroll
            for (int j = 0; j < 6; j++) {
                #pragma unroll
                for (int cr = 0; cr < 4; cr++) {
                    int row = wMs * 32 + i * 16 + g + (cr >> 1) * 8;
                    int col = wNs * 48 + j * 8 + tg * 2 + (cr & 1);
                    float v = acc_s[i][j][cr];
                    if (col < 64) {
                        sCont[row * 68 + col] = v;
                    } else {
                        int b = (col - 64) - (base_off + row);
                        if ((unsigned)b < 64u) sPB[row * 68 + b] = v;
                    }
                }
            }
        }
        __syncthreads();   // S2

        // ---- gather + online softmax (4 threads/row, 16 cols each) ----
        {
            const int q = q0 + srow;
            const float m_old = m_s[srow];
            const bool diag = (kt == qt);
            float sv[16];
            float tmax = -1e30f;
            #pragma unroll
            for (int i = 0; i < 16; i++) {
                int c = sq4 * 16 + i;
                int k = k0 + c;
                float x;
                if (diag && k > q) x = -1e30f;
                else x = (sCont[srow * 68 + c] + sPB[srow * 68 + (63 - c)]) * 0.125f;
                sv[i] = x;
                tmax = fmaxf(tmax, x);
            }
            tmax = fmaxf(tmax, __shfl_xor_sync(0xffffffffu, tmax, 1));
            tmax = fmaxf(tmax, __shfl_xor_sync(0xffffffffu, tmax, 2));
            const float m_new = fmaxf(m_old, tmax);
            float sum = 0.f;
            #pragma unroll
            for (int i = 0; i < 16; i += 2) {
                float p0 = __expf(sv[i]     - m_new);
                float p1 = __expf(sv[i + 1] - m_new);
                sum += p0 + p1;
                __half2 hp = __floats2half2_rn(p0, p1);
                sPh[srow * 36 + sq4 * 8 + (i >> 1)] = *(uint32_t*)&hp;
            }
            sum += __shfl_xor_sync(0xffffffffu, sum, 1);
            sum += __shfl_xor_sync(0xffffffffu, sum, 2);
            if (sq4 == 0) {
                float sc = __expf(m_old - m_new);
                rs[srow]  = sc;
                m_s[srow] = m_new;
                l_s[srow] = l_s[srow] * sc + sum;
            }
        }
        __syncthreads();   // S3

        // ---- prefetch next KE tile (overlaps PV MMA below) ----
        if (kt < qt) {
            const int k0n = k0 + 64;
            int dlon = q0 - k0n - 63; if (dlon < 0) dlon = 0;
            #pragma unroll
            for (int t = 0; t < 6; t++) {
                int e = tid + t * 256;
                int r = e >> 3, c8 = e & 7;
                const __half* src = (r < 64) ? Kg + (size_t)(k0n + r) * HS + c8 * 8
                                             : Eg + (size_t)(dlon + r - 64) * HS + c8 * 8;
                cpa16(uKE + (r * 36 + c8 * 4) * 4, src);
            }
            cpa_commit();
        }

        // ---- rescale O accumulator, then P @ V (fp16 HMMA) ----
        {
            const float s0 = rs[wMo * 16 + g];
            const float s1 = rs[wMo * 16 + g + 8];
            #pragma unroll
            for (int j = 0; j < 4; j++) {
                acc_o[j][0] *= s0; acc_o[j][1] *= s0;
                acc_o[j][2] *= s1; acc_o[j][3] *= s1;
            }
            #pragma unroll
            for (int ks = 0; ks < 4; ks++) {
                uint32_t af[4];
                int mr = wMo * 16;
                af[0] = sPh[(mr + g    ) * 36 + ks * 8 + tg    ];
                af[1] = sPh[(mr + g + 8) * 36 + ks * 8 + tg    ];
                af[2] = sPh[(mr + g    ) * 36 + ks * 8 + tg + 4];
                af[3] = sPh[(mr + g + 8) * 36 + ks * 8 + tg + 4];
                #pragma unroll
                for (int j = 0; j < 4; j++) {
                    int nc = wNo * 32 + j * 8 + g;
                    uint32_t bf[2] = { sVh[(ks * 8 + tg    ) * 68 + nc],
                                       sVh[(ks * 8 + tg + 4) * 68 + nc] };
                    mma16(acc_o[j], af, bf);
                }
            }
        }
    }

    // ---- epilogue: divide by l, store ----
    const int b = bn >> 4, n = bn & 15;
    const float inv0 = 1.f / l_s[wMo * 16 + g];
    const float inv1 = 1.f / l_s[wMo * 16 + g + 8];
    #pragma unroll
    for (int j = 0; j < 4; j++) {
        #pragma unroll
        for (int cr = 0; cr < 4; cr++) {
            int q = q0 + wMo * 16 + g + (cr >> 1) * 8;
            int h = wNo * 32 + j * 8 + tg * 2 + (cr & 1);
            g_O[(((size_t)b * SEQ + q) * NHEAD + n) * HS + h] =
                acc_o[j][cr] * ((cr >> 1) ? inv1 : inv0);
        }
    }
}

// ---------------- 4) out = O @ (out_kernel * scale) + bias, tf32 mma ---------
__global__ __launch_bounds__(256) void proj_kernel(
    const float* __restrict__ wk, const float* __restrict__ bias,
    float* __restrict__ out)
{
    __shared__ uint32_t sA[128][36];
    __shared__ uint32_t sB[32][136];
    const int tid = threadIdx.x, lane = tid & 31, wid = tid >> 5;
    const int g = lane >> 2, tg = lane & 3;
    const int warpN = wid & 1, warpM = wid >> 1;
    const int m0 = blockIdx.y * 128, n0 = blockIdx.x * 128;

    float acc[2][8][4] = {};
    for (int k0 = 0; k0 < DM; k0 += 32) {
        #pragma unroll
        for (int t = 0; t < 4; t++) {
            int e = tid + t * 256;
            int r = e >> 3, c = (e & 7) * 4;
            float4 v = *(const float4*)&g_O[(size_t)(m0 + r) * DM + k0 + c];
            sA[r][c] = f2t(v.x); sA[r][c+1] = f2t(v.y);
            sA[r][c+2] = f2t(v.z); sA[r][c+3] = f2t(v.w);
            int rb = e >> 5, cb = (e & 31) * 4;
            float4 u = *(const float4*)&wk[(size_t)(k0 + rb) * DM + n0 + cb];
            sB[rb][cb] = f2t(u.x); sB[rb][cb+1] = f2t(u.y);
            sB[rb][cb+2] = f2t(u.z); sB[rb][cb+3] = f2t(u.w);
        }
        __syncthreads();
        #pragma unroll
        for (int ks = 0; ks < 32; ks += 8) {
            uint32_t af[2][4];
            #pragma unroll
            for (int i = 0; i < 2; i++) {
                int mr = warpM * 32 + i * 16;
                af[i][0] = sA[mr + g    ][ks + tg    ];
                af[i][1] = sA[mr + g + 8][ks + tg    ];
                af[i][2] = sA[mr + g    ][ks + tg + 4];
                af[i][3] = sA[mr + g + 8][ks + tg + 4];
            }
            #pragma unroll
            for (int j = 0; j < 8; j++) {
                int nc = warpN * 64 + j * 8 + g;
                uint32_t bf[2] = { sB[ks + tg][nc], sB[ks + tg + 4][nc] };
                #pragma unroll
                for (int i = 0; i < 2; i++) mma8(acc[i][j], af[i], bf);
            }
        }
        __syncthreads();
    }

    const float okscale = 0.03125f;   // (1024*1024)^-0.25
    #pragma unroll
    for (int i = 0; i < 2; i++) {
        #pragma unroll
        for (int j = 0; j < 8; j++) {
            #pragma unroll
            for (int cr = 0; cr < 4; cr++) {
                int m = m0 + warpM * 32 + i * 16 + g + (cr >> 1) * 8;
                int c = n0 + warpN * 64 + j * 8 + tg * 2 + (cr & 1);
                out[(size_t)m * DM + c] = acc[i][j][cr] * okscale + bias[c];
            }
        }
    }
}

// ---------------- launcher ---------------------------------------------------
extern "C" void kernel_launch(void* const* d_in, const int* in_sizes, int n_in,
                              void* d_out, int out_size)
{
    const float* inp = (const float*)d_in[0];   // (2, 2048, 1024)
    const float* qkv = (const float*)d_in[1];   // (1024, 3, 16, 64)
    const float* qb  = (const float*)d_in[2];   // (16, 64)
    const float* pos = (const float*)d_in[3];   // (256, 16, 64)
    const float* wk  = (const float*)d_in[4];   // (1024, 1024)
    const float* ob  = (const float*)d_in[5];   // (1024,)
    float* out = (float*)d_out;                 // (2, 2048, 1024)

    const int AT_SMEM = 22592 * 4;   // 90368 B -> 2 blocks/SM
    cudaFuncSetAttribute(attn_kernel,
                         cudaFuncAttributeMaxDynamicSharedMemorySize, AT_SMEM);

    qkv_kernel<<<dim3(BN3 / 128, (BATCH * SEQ) / 128), 256>>>(inp, qkv, qb);
    emb_kernel<<<SEQ, 256>>>(pos);
    attn_kernel<<<dim3(SEQ / 64, BATCH * NHEAD), 256, AT_SMEM>>>();
    proj_kernel<<<dim3(DM / 128, (BATCH * SEQ) / 128), 256>>>(wk, ob, out);
}

// round 11
// speedup vs baseline: 2.0458x; 1.3894x over previous
#include <cuda_runtime.h>
#include <cuda_fp16.h>
#include <math.h>
#include <stdint.h>

#define BATCH 2
#define SEQ   2048
#define SEQE  (SEQ + 64)   /* emb rows padded with 64 zero rows */
#define DM    1024
#define NHEAD 16
#define HS    64
#define FQ    256
#define BN3   3072   /* 3*NHEAD*HS */

// ---------------- scratch (device globals; no allocations allowed) ----------
__device__ __half g_Qh[BATCH*NHEAD*SEQ*HS];   // [bn][s][h]
__device__ __half g_Kh[BATCH*NHEAD*SEQ*HS];   // [bn][s][h]
__device__ __half g_Vh[BATCH*NHEAD*SEQ*HS];   // packed [bn][s/2][h][2]
__device__ __half g_embh[NHEAD*SEQE*HS];      // [n][d][h], rows [SEQ,SEQE) zero
__device__ __half g_Oh[BATCH*SEQ*NHEAD*HS];   // attention output, fp16

// ---------------- mma helpers ------------------------------------------------
__device__ __forceinline__ void mma16(float c[4], const uint32_t a[4], const uint32_t b[2]) {
    asm volatile(
      "mma.sync.aligned.m16n8k16.row.col.f32.f16.f16.f32 "
      "{%0,%1,%2,%3}, {%4,%5,%6,%7}, {%8,%9}, {%0,%1,%2,%3};"
      : "+f"(c[0]), "+f"(c[1]), "+f"(c[2]), "+f"(c[3])
      : "r"(a[0]), "r"(a[1]), "r"(a[2]), "r"(a[3]), "r"(b[0]), "r"(b[1]));
}
__device__ __forceinline__ void cpa16(uint32_t dst, const void* src) {
    asm volatile("cp.async.cg.shared.global [%0], [%1], 16;" :: "r"(dst), "l"(src));
}
__device__ __forceinline__ void cpa_commit() {
    asm volatile("cp.async.commit_group;");
}
__device__ __forceinline__ void cpa_wait0() {
    asm volatile("cp.async.wait_group 0;");
}
__device__ __forceinline__ uint32_t h2u(__half2 h) { return *(uint32_t*)&h; }

// ---------------- 1) QKV projection: (4096x1024) @ (1024x3072), fp16 mma ----
__global__ __launch_bounds__(256) void qkv_kernel(
    const float* __restrict__ inp, const float* __restrict__ w,
    const float* __restrict__ qb)
{
    __shared__ uint32_t sAh[128][20];   // [m][k-pair], stride 20: conflict-free
    __shared__ uint32_t sBh[16][136];   // [k-pair][n], stride 136: conflict-free
    const int tid = threadIdx.x, lane = tid & 31, wid = tid >> 5;
    const int g = lane >> 2, tg = lane & 3;
    const int warpN = wid & 1, warpM = wid >> 1;   // warp tile 32x64
    const int m0 = blockIdx.y * 128, n0 = blockIdx.x * 128;

    float acc[2][8][4] = {};
    for (int k0 = 0; k0 < DM; k0 += 32) {
        // A: 128x32 fp32 -> half-pair words
        #pragma unroll
        for (int t = 0; t < 4; t++) {
            int e = tid + t * 256;
            int r = e >> 3, c4 = (e & 7) * 4;
            float4 v = *(const float4*)&inp[(size_t)(m0 + r) * DM + k0 + c4];
            sAh[r][(e & 7) * 2    ] = h2u(__floats2half2_rn(v.x, v.y));
            sAh[r][(e & 7) * 2 + 1] = h2u(__floats2half2_rn(v.z, v.w));
        }
        // B: 32x128 fp32 -> k-pair words [16][128]
        #pragma unroll
        for (int t = 0; t < 2; t++) {
            int e = tid + t * 256;
            int rb = e >> 5, cb = (e & 31) * 4;
            float4 u0 = *(const float4*)&w[(size_t)(k0 + 2*rb    ) * BN3 + n0 + cb];
            float4 u1 = *(const float4*)&w[(size_t)(k0 + 2*rb + 1) * BN3 + n0 + cb];
            sBh[rb][cb    ] = h2u(__floats2half2_rn(u0.x, u1.x));
            sBh[rb][cb + 1] = h2u(__floats2half2_rn(u0.y, u1.y));
            sBh[rb][cb + 2] = h2u(__floats2half2_rn(u0.z, u1.z));
            sBh[rb][cb + 3] = h2u(__floats2half2_rn(u0.w, u1.w));
        }
        __syncthreads();
        #pragma unroll
        for (int ks = 0; ks < 2; ks++) {
            uint32_t af[2][4];
            #pragma unroll
            for (int i = 0; i < 2; i++) {
                int mr = warpM * 32 + i * 16;
                af[i][0] = sAh[mr + g    ][ks * 8 + tg    ];
                af[i][1] = sAh[mr + g + 8][ks * 8 + tg    ];
                af[i][2] = sAh[mr + g    ][ks * 8 + tg + 4];
                af[i][3] = sAh[mr + g + 8][ks * 8 + tg + 4];
            }
            #pragma unroll
            for (int j = 0; j < 8; j++) {
                int nc = warpN * 64 + j * 8 + g;
                uint32_t bf[2] = { sBh[ks * 8 + tg][nc], sBh[ks * 8 + tg + 4][nc] };
                #pragma unroll
                for (int i = 0; i < 2; i++) mma16(acc[i][j], af[i], bf);
            }
        }
        __syncthreads();
    }

    const float qscale = powf(3.0f * DM * NHEAD * HS, -0.25f);
    #pragma unroll
    for (int i = 0; i < 2; i++) {
        #pragma unroll
        for (int j = 0; j < 8; j++) {
            #pragma unroll
            for (int cr = 0; cr < 4; cr++) {
                int m = m0 + warpM * 32 + i * 16 + g + (cr >> 1) * 8;
                int c = n0 + warpN * 64 + j * 8 + tg * 2 + (cr & 1);
                int b = m >> 11, s = m & (SEQ - 1);
                int A = c >> 10, n = (c >> 6) & 15, h = c & 63;
                float v = acc[i][j][cr] * qscale;
                size_t bn = (size_t)(b * NHEAD + n);
                if (A == 0)
                    g_Qh[(bn * SEQ + s) * HS + h] = __float2half_rn(v + qb[n * HS + h]);
                else if (A == 1)
                    g_Kh[(bn * SEQ + s) * HS + h] = __float2half_rn(v);
                else
                    g_Vh[((bn * (SEQ/2) + (s >> 1)) * HS + h) * 2 + (s & 1)] = __float2half_rn(v);
            }
        }
    }
}

// ---------------- 2) relative-position embedding table (fp16 out) -----------
__global__ __launch_bounds__(256) void emb_kernel(const float* __restrict__ pos)
{
    __shared__ float ssin[FQ];
    const int s = blockIdx.x;
    const int tid = threadIdx.x;
    {
        int f = tid;
        double inv = pow(10000.0, -(double)((f >> 1) * 2) / (double)FQ);
        double ang = (double)s * inv;
        double v = (f & 1) ? cos(ang) : sin(ang);
        ssin[f] = (float)(1.4142135623730951 * v);
    }
    __syncthreads();

    int c4 = tid * 4;
    float a0 = 0.f, a1 = 0.f, a2 = 0.f, a3 = 0.f;
    for (int f = 0; f < FQ; f++) {
        float4 p = *reinterpret_cast<const float4*>(&pos[(size_t)f * (NHEAD * HS) + c4]);
        float sv = ssin[f];
        a0 += sv * p.x; a1 += sv * p.y; a2 += sv * p.z; a3 += sv * p.w;
    }
    const float pscale = 0.0625f;
    int n = c4 >> 6, h = c4 & 63;
    size_t base = ((size_t)n * SEQE + s) * HS + h;
    g_embh[base + 0] = __float2half_rn(a0 * pscale);
    g_embh[base + 1] = __float2half_rn(a1 * pscale);
    g_embh[base + 2] = __float2half_rn(a2 * pscale);
    g_embh[base + 3] = __float2half_rn(a3 * pscale);
}

// ---------------- 3) fused flash attention, register-resident content -------
// QK warp grid 4x2 (warp tile 16x96): each row's 64 content columns stay in
// one warp's accumulators; only the positional panel round-trips via SMEM.
// SMEM word layout (dynamic), 18624 words = 74496 B (2 blocks/SM):
//   sQh   [64][36]  h-pair words, persistent   @ 0
//   sKEh  [192][36] (K rows 0-63, E 64-191)    @ 2304
//   sPB   [64][72]  fp32 banded pos panel      @ 9216
//   sPh   [64][36]  P fp16 k-pair words        @ 13824
//   sVh   [32][72]  V k-pair words             @ 16128
//   m_s/l_s/rs [64] each                       @ 18432
extern __shared__ uint32_t smw[];
__global__ __launch_bounds__(256, 2) void attn_kernel()
{
    const int qt = (SEQ / 64 - 1) - blockIdx.x;   // longest blocks first
    const int bn = blockIdx.y;
    const int q0 = qt * 64;

    uint32_t* sQh  = smw;
    uint32_t* sKEh = smw + 2304;
    float*    sPB  = (float*)(smw + 9216);
    uint32_t* sPh  = smw + 13824;
    uint32_t* sVh  = smw + 16128;
    float*    m_s  = (float*)(smw + 18432);
    float*    l_s  = m_s + 64;
    float*    rs   = m_s + 128;

    const uint32_t* Qg = (const uint32_t*)g_Qh + (size_t)bn * SEQ * (HS/2);
    const __half*   Kg = g_Kh + (size_t)bn * SEQ * HS;
    const uint32_t* Vg = (const uint32_t*)g_Vh + (size_t)bn * (SEQ/2) * HS;
    const int hd = bn & (NHEAD - 1);
    const __half*   Eg = g_embh + (size_t)hd * SEQE * HS;

    const uint32_t uKE = (uint32_t)__cvta_generic_to_shared(sKEh);

    const int tid = threadIdx.x, lane = tid & 31, wid = tid >> 5;
    const int g = lane >> 2, tg = lane & 3;
    const int wMs = wid & 3, wNs = wid >> 2;   // QK: 4x2 grid, tile 16x96
    // PV uses the same 4x2 mapping: tile 16x32

    // load Q tile (h-pair words) + init state
    #pragma unroll
    for (int t = 0; t < 2; t++) {
        int e = tid + t * 256;
        int r = e >> 3, c = (e & 7) * 4;
        *(uint4*)&sQh[r * 36 + c] = *(const uint4*)&Qg[(size_t)(q0 + r) * (HS/2) + c];
    }
    if (tid < 64) { m_s[tid] = -1e30f; l_s[tid] = 0.f; }

    // prologue: prefetch KE tile for kt=0 (16B = 8 halves per chunk)
    {
        int dlo = q0 - 63; if (dlo < 0) dlo = 0;
        #pragma unroll
        for (int t = 0; t < 6; t++) {
            int e = tid + t * 256;
            int r = e >> 3, c8 = e & 7;
            const __half* src = (r < 64) ? Kg + (size_t)r * HS + c8 * 8
                                         : Eg + (size_t)(dlo + r - 64) * HS + c8 * 8;
            cpa16(uKE + (r * 36 + c8 * 4) * 4, src);
        }
        cpa_commit();
    }

    float acc_o[4][4] = {};

    for (int kt = 0; kt <= qt; kt++) {
        const int k0 = kt * 64;
        int dlo = q0 - k0 - 63; if (dlo < 0) dlo = 0;
        const int base_off = q0 - k0 - 63 - dlo;   // 0 except diag tile (-63)

        __syncthreads();   // S0: prior PV reads of sPh/sVh done

        // ---- V load (k-pair packed rows, 16B copies) ----
        #pragma unroll
        for (int t = 0; t < 2; t++) {
            int e = tid + t * 256;
            int r = e >> 4, c = (e & 15) * 4;
            *(uint4*)&sVh[r * 72 + c] = *(const uint4*)&Vg[(size_t)((k0 >> 1) + r) * HS + c];
        }
        cpa_wait0();       // KE tile for this kt has landed
        __syncthreads();   // S1

        // ---- fused QK^T / Q@E^T HMMA: 64 x 192, warp tile 16x96 ----
        float acc_s[12][4] = {};
        #pragma unroll
        for (int ks = 0; ks < 4; ks++) {
            uint32_t af[4];
            int mr = wMs * 16;
            af[0] = sQh[(mr + g    ) * 36 + ks * 8 + tg    ];
            af[1] = sQh[(mr + g + 8) * 36 + ks * 8 + tg    ];
            af[2] = sQh[(mr + g    ) * 36 + ks * 8 + tg + 4];
            af[3] = sQh[(mr + g + 8) * 36 + ks * 8 + tg + 4];
            #pragma unroll
            for (int j = 0; j < 12; j++) {
                int nc = wNs * 96 + j * 8 + g;
                uint32_t bf[2] = { sKEh[nc * 36 + ks * 8 + tg],
                                   sKEh[nc * 36 + ks * 8 + tg + 4] };
                mma16(acc_s[j], af, bf);
            }
        }

        // ---- scatter positional cols (>=64) into banded sPB ----
        #pragma unroll
        for (int j = 0; j < 12; j++) {
            int colbase = wNs * 96 + j * 8;
            if (colbase + 7 < 64) continue;   // content-only n-tile (compile-time)
            #pragma unroll
            for (int cr = 0; cr < 4; cr++) {
                int row = wMs * 16 + g + (cr >> 1) * 8;
                int col = colbase + tg * 2 + (cr & 1);
                int b = (col - 64) - (base_off + row);
                if ((unsigned)b < 64u) sPB[row * 72 + b] = acc_s[j][cr];
            }
        }
        __syncthreads();   // S2

        // ---- register softmax (wNs==0 warps own all content cols) ----
        if (wNs == 0) {
            const int r0 = wMs * 16 + g, r1 = r0 + 8;
            const int qq0 = q0 + r0, qq1 = q0 + r1;
            const bool diag = (kt == qt);
            const float m_old0 = m_s[r0], m_old1 = m_s[r1];
            float mx0 = -1e30f, mx1 = -1e30f;
            #pragma unroll
            for (int j = 0; j < 8; j++) {
                #pragma unroll
                for (int b2 = 0; b2 < 2; b2++) {
                    int c = j * 8 + tg * 2 + b2;
                    int k = k0 + c;
                    float x0 = (diag && k > qq0) ? -1e30f
                             : (acc_s[j][b2]     + sPB[r0 * 72 + 63 - c]) * 0.125f;
                    float x1 = (diag && k > qq1) ? -1e30f
                             : (acc_s[j][2 + b2] + sPB[r1 * 72 + 63 - c]) * 0.125f;
                    acc_s[j][b2] = x0; acc_s[j][2 + b2] = x1;
                    mx0 = fmaxf(mx0, x0); mx1 = fmaxf(mx1, x1);
                }
            }
            mx0 = fmaxf(mx0, __shfl_xor_sync(0xffffffffu, mx0, 1));
            mx0 = fmaxf(mx0, __shfl_xor_sync(0xffffffffu, mx0, 2));
            mx1 = fmaxf(mx1, __shfl_xor_sync(0xffffffffu, mx1, 1));
            mx1 = fmaxf(mx1, __shfl_xor_sync(0xffffffffu, mx1, 2));
            const float mn0 = fmaxf(m_old0, mx0);
            const float mn1 = fmaxf(m_old1, mx1);
            float s0 = 0.f, s1 = 0.f;
            #pragma unroll
            for (int j = 0; j < 8; j++) {
                float p00 = __expf(acc_s[j][0] - mn0);
                float p01 = __expf(acc_s[j][1] - mn0);
                float p10 = __expf(acc_s[j][2] - mn1);
                float p11 = __expf(acc_s[j][3] - mn1);
                s0 += p00 + p01; s1 += p10 + p11;
                sPh[r0 * 36 + 4 * j + tg] = h2u(__floats2half2_rn(p00, p01));
                sPh[r1 * 36 + 4 * j + tg] = h2u(__floats2half2_rn(p10, p11));
            }
            s0 += __shfl_xor_sync(0xffffffffu, s0, 1);
            s0 += __shfl_xor_sync(0xffffffffu, s0, 2);
            s1 += __shfl_xor_sync(0xffffffffu, s1, 1);
            s1 += __shfl_xor_sync(0xffffffffu, s1, 2);
            if (tg == 0) {
                float sc0 = __expf(m_old0 - mn0);
                float sc1 = __expf(m_old1 - mn1);
                rs[r0] = sc0; m_s[r0] = mn0; l_s[r0] = l_s[r0] * sc0 + s0;
                rs[r1] = sc1; m_s[r1] = mn1; l_s[r1] = l_s[r1] * sc1 + s1;
            }
        }
        __syncthreads();   // S3

        // ---- prefetch next KE tile (overlaps PV MMA below) ----
        if (kt < qt) {
            const int k0n = k0 + 64;
            int dlon = q0 - k0n - 63; if (dlon < 0) dlon = 0;
            #pragma unroll
            for (int t = 0; t < 6; t++) {
                int e = tid + t * 256;
                int r = e >> 3, c8 = e & 7;
                const __half* src = (r < 64) ? Kg + (size_t)(k0n + r) * HS + c8 * 8
                                             : Eg + (size_t)(dlon + r - 64) * HS + c8 * 8;
                cpa16(uKE + (r * 36 + c8 * 4) * 4, src);
            }
            cpa_commit();
        }

        // ---- rescale O accumulator, then P @ V (fp16 HMMA, tile 16x32) ----
        {
            const float s0 = rs[wMs * 16 + g];
            const float s1 = rs[wMs * 16 + g + 8];
            #pragma unroll
            for (int j = 0; j < 4; j++) {
                acc_o[j][0] *= s0; acc_o[j][1] *= s0;
                acc_o[j][2] *= s1; acc_o[j][3] *= s1;
            }
            #pragma unroll
            for (int ks = 0; ks < 4; ks++) {
                uint32_t af[4];
                int mr = wMs * 16;
                af[0] = sPh[(mr + g    ) * 36 + ks * 8 + tg    ];
                af[1] = sPh[(mr + g + 8) * 36 + ks * 8 + tg    ];
                af[2] = sPh[(mr + g    ) * 36 + ks * 8 + tg + 4];
                af[3] = sPh[(mr + g + 8) * 36 + ks * 8 + tg + 4];
                #pragma unroll
                for (int j = 0; j < 4; j++) {
                    int nc = wNs * 32 + j * 8 + g;
                    uint32_t bf[2] = { sVh[(ks * 8 + tg    ) * 72 + nc],
                                       sVh[(ks * 8 + tg + 4) * 72 + nc] };
                    mma16(acc_o[j], af, bf);
                }
            }
        }
    }

    // ---- epilogue: divide by l, store fp16 ----
    const int b = bn >> 4, n = bn & 15;
    const float inv0 = 1.f / l_s[wMs * 16 + g];
    const float inv1 = 1.f / l_s[wMs * 16 + g + 8];
    #pragma unroll
    for (int j = 0; j < 4; j++) {
        #pragma unroll
        for (int cr = 0; cr < 4; cr++) {
            int q = q0 + wMs * 16 + g + (cr >> 1) * 8;
            int h = wNs * 32 + j * 8 + tg * 2 + (cr & 1);
            g_Oh[(((size_t)b * SEQ + q) * NHEAD + n) * HS + h] =
                __float2half_rn(acc_o[j][cr] * ((cr >> 1) ? inv1 : inv0));
        }
    }
}

// ---------------- 4) out = O @ (out_kernel * scale) + bias, fp16 mma --------
__global__ __launch_bounds__(256) void proj_kernel(
    const float* __restrict__ wk, const float* __restrict__ bias,
    float* __restrict__ out)
{
    __shared__ uint32_t sAh[128][20];
    __shared__ uint32_t sBh[16][136];
    const int tid = threadIdx.x, lane = tid & 31, wid = tid >> 5;
    const int g = lane >> 2, tg = lane & 3;
    const int warpN = wid & 1, warpM = wid >> 1;
    const int m0 = blockIdx.y * 128, n0 = blockIdx.x * 128;

    float acc[2][8][4] = {};
    for (int k0 = 0; k0 < DM; k0 += 32) {
        // A: raw fp16 copies from g_Oh
        #pragma unroll
        for (int t = 0; t < 2; t++) {
            int e = tid + t * 256;
            int r = e >> 2, w4 = (e & 3) * 4;
            *(uint4*)&sAh[r][w4] =
                *(const uint4*)&g_Oh[(size_t)(m0 + r) * DM + k0 + (e & 3) * 8];
        }
        // B: 32x128 fp32 -> k-pair words
        #pragma unroll
        for (int t = 0; t < 2; t++) {
            int e = tid + t * 256;
            int rb = e >> 5, cb = (e & 31) * 4;
            float4 u0 = *(const float4*)&wk[(size_t)(k0 + 2*rb    ) * DM + n0 + cb];
            float4 u1 = *(const float4*)&wk[(size_t)(k0 + 2*rb + 1) * DM + n0 + cb];
            sBh[rb][cb    ] = h2u(__floats2half2_rn(u0.x, u1.x));
            sBh[rb][cb + 1] = h2u(__floats2half2_rn(u0.y, u1.y));
            sBh[rb][cb + 2] = h2u(__floats2half2_rn(u0.z, u1.z));
            sBh[rb][cb + 3] = h2u(__floats2half2_rn(u0.w, u1.w));
        }
        __syncthreads();
        #pragma unroll
        for (int ks = 0; ks < 2; ks++) {
            uint32_t af[2][4];
            #pragma unroll
            for (int i = 0; i < 2; i++) {
                int mr = warpM * 32 + i * 16;
                af[i][0] = sAh[mr + g    ][ks * 8 + tg    ];
                af[i][1] = sAh[mr + g + 8][ks * 8 + tg    ];
                af[i][2] = sAh[mr + g    ][ks * 8 + tg + 4];
                af[i][3] = sAh[mr + g + 8][ks * 8 + tg + 4];
            }
            #pragma unroll
            for (int j = 0; j < 8; j++) {
                int nc = warpN * 64 + j * 8 + g;
                uint32_t bf[2] = { sBh[ks * 8 + tg][nc], sBh[ks * 8 + tg + 4][nc] };
                #pragma unroll
                for (int i = 0; i < 2; i++) mma16(acc[i][j], af[i], bf);
            }
        }
        __syncthreads();
    }

    const float okscale = 0.03125f;   // (1024*1024)^-0.25
    #pragma unroll
    for (int i = 0; i < 2; i++) {
        #pragma unroll
        for (int j = 0; j < 8; j++) {
            #pragma unroll
            for (int cr = 0; cr < 4; cr++) {
                int m = m0 + warpM * 32 + i * 16 + g + (cr >> 1) * 8;
                int c = n0 + warpN * 64 + j * 8 + tg * 2 + (cr & 1);
                out[(size_t)m * DM + c] = acc[i][j][cr] * okscale + bias[c];
            }
        }
    }
}

// ---------------- launcher ---------------------------------------------------
extern "C" void kernel_launch(void* const* d_in, const int* in_sizes, int n_in,
                              void* d_out, int out_size)
{
    const float* inp = (const float*)d_in[0];   // (2, 2048, 1024)
    const float* qkv = (const float*)d_in[1];   // (1024, 3, 16, 64)
    const float* qb  = (const float*)d_in[2];   // (16, 64)
    const float* pos = (const float*)d_in[3];   // (256, 16, 64)
    const float* wk  = (const float*)d_in[4];   // (1024, 1024)
    const float* ob  = (const float*)d_in[5];   // (1024,)
    float* out = (float*)d_out;                 // (2, 2048, 1024)

    const int AT_SMEM = 18624 * 4;   // 74496 B -> 2 blocks/SM
    cudaFuncSetAttribute(attn_kernel,
                         cudaFuncAttributeMaxDynamicSharedMemorySize, AT_SMEM);

    qkv_kernel<<<dim3(BN3 / 128, (BATCH * SEQ) / 128), 256>>>(inp, qkv, qb);
    emb_kernel<<<SEQ, 256>>>(pos);
    attn_kernel<<<dim3(SEQ / 64, BATCH * NHEAD), 256, AT_SMEM>>>();
    proj_kernel<<<dim3(DM / 128, (BATCH * SEQ) / 128), 256>>>(wk, ob, out);
}

// round 13
// speedup vs baseline: 2.2863x; 1.1176x over previous
#include <cuda_runtime.h>
#include <cuda_fp16.h>
#include <math.h>
#include <stdint.h>

#define BATCH 2
#define SEQ   2048
#define SEQE  (SEQ + 64)   /* emb rows padded with 64 zero rows */
#define DM    1024
#define NHEAD 16
#define HS    64
#define FQ    256
#define BN3   3072   /* 3*NHEAD*HS */

// ---------------- scratch (device globals; no allocations allowed) ----------
__device__ __half g_inph[BATCH*SEQ*DM];       // fp16 copy of input
__device__ __half g_wh[DM*BN3];               // fp16 copy of qkv weight
__device__ __half g_wkh[DM*DM];               // fp16 copy of out_kernel
__device__ __half g_Qh[BATCH*NHEAD*SEQ*HS];   // [bn][s][h]
__device__ __half g_Kh[BATCH*NHEAD*SEQ*HS];   // [bn][s][h]
__device__ __half g_Vh[BATCH*NHEAD*SEQ*HS];   // plain [bn][s][h]
__device__ __half g_embh[NHEAD*SEQE*HS];      // [n][d][h], rows [SEQ,SEQE) zero
__device__ __half g_Oh[BATCH*SEQ*NHEAD*HS];   // attention output, fp16

// ---------------- helpers -----------------------------------------------------
__device__ __forceinline__ void mma16(float c[4], const uint32_t a[4], const uint32_t b[2]) {
    asm volatile(
      "mma.sync.aligned.m16n8k16.row.col.f32.f16.f16.f32 "
      "{%0,%1,%2,%3}, {%4,%5,%6,%7}, {%8,%9}, {%0,%1,%2,%3};"
      : "+f"(c[0]), "+f"(c[1]), "+f"(c[2]), "+f"(c[3])
      : "r"(a[0]), "r"(a[1]), "r"(a[2]), "r"(a[3]), "r"(b[0]), "r"(b[1]));
}
__device__ __forceinline__ void ldsm4(uint32_t r[4], uint32_t saddr) {
    asm volatile("ldmatrix.sync.aligned.m8n8.x4.shared.b16 {%0,%1,%2,%3}, [%4];"
      : "=r"(r[0]), "=r"(r[1]), "=r"(r[2]), "=r"(r[3]) : "r"(saddr));
}
__device__ __forceinline__ void ldsm4t(uint32_t r[4], uint32_t saddr) {
    asm volatile("ldmatrix.sync.aligned.m8n8.x4.trans.shared.b16 {%0,%1,%2,%3}, [%4];"
      : "=r"(r[0]), "=r"(r[1]), "=r"(r[2]), "=r"(r[3]) : "r"(saddr));
}
__device__ __forceinline__ void cpa16(uint32_t dst, const void* src) {
    asm volatile("cp.async.cg.shared.global [%0], [%1], 16;" :: "r"(dst), "l"(src));
}
__device__ __forceinline__ void cpa_commit() { asm volatile("cp.async.commit_group;"); }
__device__ __forceinline__ void cpa_wait0()  { asm volatile("cp.async.wait_group 0;"); }
__device__ __forceinline__ uint32_t h2u(__half2 h) { return *(uint32_t*)&h; }

// ---------------- 0) fp32 -> fp16 converter ----------------------------------
__global__ __launch_bounds__(256) void cvt_kernel(
    const float4* __restrict__ src, uint2* __restrict__ dst, int n4)
{
    int i = blockIdx.x * 256 + threadIdx.x;
    if (i < n4) {
        float4 v = src[i];
        uint2 o;
        o.x = h2u(__floats2half2_rn(v.x, v.y));
        o.y = h2u(__floats2half2_rn(v.z, v.w));
        dst[i] = o;
    }
}

// ---------------- 1) QKV projection: fp16 in, ldmatrix, k-tile 64 ------------
__global__ __launch_bounds__(256) void qkv_kernel(const float* __restrict__ qb)
{
    __shared__ __align__(16) __half sA[128 * 72];    // [m][k] rows
    __shared__ __align__(16) __half sB[64 * 136];    // [k][n] rows
    const int tid = threadIdx.x, lane = tid & 31, wid = tid >> 5;
    const int g = lane >> 2, tg = lane & 3;
    const int warpN = wid & 1, warpM = wid >> 1;     // warp tile 32x64
    const int m0 = blockIdx.y * 128, n0 = blockIdx.x * 128;
    const uint32_t aA = (uint32_t)__cvta_generic_to_shared(sA);
    const uint32_t aB = (uint32_t)__cvta_generic_to_shared(sB);
    const int l15 = lane & 15, lh = (lane & 16) >> 1;   // lh = 8 for upper half

    float acc[2][8][4] = {};
    for (int k0 = 0; k0 < DM; k0 += 64) {
        #pragma unroll
        for (int t = 0; t < 4; t++) {
            int e = tid + t * 256;
            int r = e >> 3, c = (e & 7) * 8;
            *(uint4*)&sA[r * 72 + c] = *(const uint4*)&g_inph[(size_t)(m0 + r) * DM + k0 + c];
        }
        #pragma unroll
        for (int t = 0; t < 4; t++) {
            int e = tid + t * 256;
            int r = e >> 4, c = (e & 15) * 8;
            *(uint4*)&sB[r * 136 + c] = *(const uint4*)&g_wh[(size_t)(k0 + r) * BN3 + n0 + c];
        }
        __syncthreads();
        #pragma unroll
        for (int ks = 0; ks < 4; ks++) {
            uint32_t af[2][4];
            #pragma unroll
            for (int i = 0; i < 2; i++) {
                int mr = warpM * 32 + i * 16;
                ldsm4(af[i], aA + ((mr + l15) * 72 + ks * 16 + lh) * 2);
            }
            #pragma unroll
            for (int jp = 0; jp < 4; jp++) {
                int nj = warpN * 64 + jp * 16;
                uint32_t bq[4];
                ldsm4t(bq, aB + ((ks * 16 + l15) * 136 + nj + lh) * 2);
                mma16(acc[0][2*jp],   af[0], bq);
                mma16(acc[0][2*jp+1], af[0], bq + 2);
                mma16(acc[1][2*jp],   af[1], bq);
                mma16(acc[1][2*jp+1], af[1], bq + 2);
            }
        }
        __syncthreads();
    }

    const float qscale = powf(3.0f * DM * NHEAD * HS, -0.25f);
    #pragma unroll
    for (int i = 0; i < 2; i++) {
        #pragma unroll
        for (int j = 0; j < 8; j++) {
            #pragma unroll
            for (int cr = 0; cr < 4; cr++) {
                int m = m0 + warpM * 32 + i * 16 + g + (cr >> 1) * 8;
                int c = n0 + warpN * 64 + j * 8 + tg * 2 + (cr & 1);
                int b = m >> 11, s = m & (SEQ - 1);
                int A = c >> 10, n = (c >> 6) & 15, h = c & 63;
                float v = acc[i][j][cr] * qscale;
                size_t bn = (size_t)(b * NHEAD + n);
                if (A == 0)
                    g_Qh[(bn * SEQ + s) * HS + h] = __float2half_rn(v + qb[n * HS + h]);
                else if (A == 1)
                    g_Kh[(bn * SEQ + s) * HS + h] = __float2half_rn(v);
                else
                    g_Vh[(bn * SEQ + s) * HS + h] = __float2half_rn(v);
            }
        }
    }
}

// ---------------- 2) relative-position embedding table (fp16 out) -----------
__global__ __launch_bounds__(256) void emb_kernel(const float* __restrict__ pos)
{
    __shared__ float ssin[FQ];
    const int s = blockIdx.x;
    const int tid = threadIdx.x;
    {
        int f = tid;
        double inv = pow(10000.0, -(double)((f >> 1) * 2) / (double)FQ);
        double ang = (double)s * inv;
        double v = (f & 1) ? cos(ang) : sin(ang);
        ssin[f] = (float)(1.4142135623730951 * v);
    }
    __syncthreads();

    int c4 = tid * 4;
    float a0 = 0.f, a1 = 0.f, a2 = 0.f, a3 = 0.f;
    for (int f = 0; f < FQ; f++) {
        float4 p = *reinterpret_cast<const float4*>(&pos[(size_t)f * (NHEAD * HS) + c4]);
        float sv = ssin[f];
        a0 += sv * p.x; a1 += sv * p.y; a2 += sv * p.z; a3 += sv * p.w;
    }
    const float pscale = 0.0625f;
    int n = c4 >> 6, h = c4 & 63;
    size_t base = ((size_t)n * SEQE + s) * HS + h;
    g_embh[base + 0] = __float2half_rn(a0 * pscale);
    g_embh[base + 1] = __float2half_rn(a1 * pscale);
    g_embh[base + 2] = __float2half_rn(a2 * pscale);
    g_embh[base + 3] = __float2half_rn(a3 * pscale);
}

// ---------------- 3) fused flash attention, ldmatrix fragments --------------
// SMEM word layout (dynamic), 18624 words = 74496 B (2 blocks/SM):
//   sQh   [64][36w]  h-pair words, persistent  @ 0
//   sKEh  [192][36w] (K rows 0-63, E 64-191)   @ 2304
//   sPB   [64][72]   fp32 banded pos panel     @ 9216
//   sPh   [64][36w]  P fp16 k-pair words       @ 13824
//   sVh   [64][36w]  V plain rows [k][h]       @ 16128
//   m_s/l_s/rs [64] each                       @ 18432
extern __shared__ uint32_t smw[];
__global__ __launch_bounds__(256, 2) void attn_kernel()
{
    const int qt = (SEQ / 64 - 1) - blockIdx.x;   // longest blocks first
    const int bn = blockIdx.y;
    const int q0 = qt * 64;

    uint32_t* sQh  = smw;
    uint32_t* sKEh = smw + 2304;
    float*    sPB  = (float*)(smw + 9216);
    uint32_t* sPh  = smw + 13824;
    __half*   sVhh = (__half*)(smw + 16128);
    float*    m_s  = (float*)(smw + 18432);
    float*    l_s  = m_s + 64;
    float*    rs   = m_s + 128;

    const uint32_t* Qg = (const uint32_t*)g_Qh + (size_t)bn * SEQ * (HS/2);
    const __half*   Kg = g_Kh + (size_t)bn * SEQ * HS;
    const __half*   Vg = g_Vh + (size_t)bn * SEQ * HS;
    const int hd = bn & (NHEAD - 1);
    const __half*   Eg = g_embh + (size_t)hd * SEQE * HS;

    const uint32_t aQ  = (uint32_t)__cvta_generic_to_shared(sQh);
    const uint32_t aKE = (uint32_t)__cvta_generic_to_shared(sKEh);
    const uint32_t aP  = (uint32_t)__cvta_generic_to_shared(sPh);
    const uint32_t aV  = (uint32_t)__cvta_generic_to_shared(sVhh);

    const int tid = threadIdx.x, lane = tid & 31, wid = tid >> 5;
    const int g = lane >> 2, tg = lane & 3;
    const int wMs = wid & 3, wNs = wid >> 2;   // QK: 4x2 grid, tile 16x96; PV 16x32
    const int l15 = lane & 15, l8 = lane & 8, lh = (lane & 16) >> 1;
    const int l7 = lane & 7;

    // load Q tile (h-pair words) + init state
    #pragma unroll
    for (int t = 0; t < 2; t++) {
        int e = tid + t * 256;
        int r = e >> 3, c = (e & 7) * 4;
        *(uint4*)&sQh[r * 36 + c] = *(const uint4*)&Qg[(size_t)(q0 + r) * (HS/2) + c];
    }
    if (tid < 64) { m_s[tid] = -1e30f; l_s[tid] = 0.f; }

    // prologue: prefetch KE tile for kt=0
    {
        int dlo = q0 - 63; if (dlo < 0) dlo = 0;
        #pragma unroll
        for (int t = 0; t < 6; t++) {
            int e = tid + t * 256;
            int r = e >> 3, c8 = e & 7;
            const __half* src = (r < 64) ? Kg + (size_t)r * HS + c8 * 8
                                         : Eg + (size_t)(dlo + r - 64) * HS + c8 * 8;
            cpa16(aKE + (r * 36 + c8 * 4) * 4, src);
        }
        cpa_commit();
    }

    float acc_o[4][4] = {};

    for (int kt = 0; kt <= qt; kt++) {
        const int k0 = kt * 64;
        int dlo = q0 - k0 - 63; if (dlo < 0) dlo = 0;
        const int base_off = q0 - k0 - 63 - dlo;   // 0 except diag tile (-63)

        __syncthreads();   // S0: prior PV reads of sPh/sVh done

        // ---- V load (plain rows, 16B copies) ----
        #pragma unroll
        for (int t = 0; t < 2; t++) {
            int e = tid + t * 256;
            int r = e >> 3, c = (e & 7) * 8;
            *(uint4*)&sVhh[r * 72 + c] = *(const uint4*)&Vg[(size_t)(k0 + r) * HS + c];
        }
        cpa_wait0();       // KE tile for this kt has landed
        __syncthreads();   // S1

        // ---- fused QK^T / Q@E^T HMMA: 64x192, warp tile 16x96, ldmatrix ----
        float acc_s[12][4] = {};
        #pragma unroll
        for (int ks = 0; ks < 4; ks++) {
            uint32_t af[4];
            ldsm4(af, aQ + ((wMs * 16 + l15) * 72 + ks * 16 + lh) * 2);
            #pragma unroll
            for (int jp = 0; jp < 6; jp++) {
                int nc0 = wNs * 96 + jp * 16;
                uint32_t bq[4];
                ldsm4(bq, aKE + ((nc0 + l7 + lh) * 72 + ks * 16 + l8) * 2);
                mma16(acc_s[2*jp],   af, bq);
                mma16(acc_s[2*jp+1], af, bq + 2);
            }
        }

        // ---- scatter positional cols (>=64) into banded sPB ----
        #pragma unroll
        for (int j = 0; j < 12; j++) {
            int colbase = wNs * 96 + j * 8;
            if (colbase + 7 < 64) continue;   // content-only n-tile (compile-time)
            #pragma unroll
            for (int cr = 0; cr < 4; cr++) {
                int row = wMs * 16 + g + (cr >> 1) * 8;
                int col = colbase + tg * 2 + (cr & 1);
                int b = (col - 64) - (base_off + row);
                if ((unsigned)b < 64u) sPB[row * 72 + b] = acc_s[j][cr];
            }
        }
        __syncthreads();   // S2

        // ---- register softmax (wNs==0 warps own all content cols) ----
        if (wNs == 0) {
            const int r0 = wMs * 16 + g, r1 = r0 + 8;
            const int qq0 = q0 + r0, qq1 = q0 + r1;
            const bool diag = (kt == qt);
            const float m_old0 = m_s[r0], m_old1 = m_s[r1];
            float mx0 = -1e30f, mx1 = -1e30f;
            #pragma unroll
            for (int j = 0; j < 8; j++) {
                #pragma unroll
                for (int b2 = 0; b2 < 2; b2++) {
                    int c = j * 8 + tg * 2 + b2;
                    int k = k0 + c;
                    float x0 = (diag && k > qq0) ? -1e30f
                             : (acc_s[j][b2]     + sPB[r0 * 72 + 63 - c]) * 0.125f;
                    float x1 = (diag && k > qq1) ? -1e30f
                             : (acc_s[j][2 + b2] + sPB[r1 * 72 + 63 - c]) * 0.125f;
                    acc_s[j][b2] = x0; acc_s[j][2 + b2] = x1;
                    mx0 = fmaxf(mx0, x0); mx1 = fmaxf(mx1, x1);
                }
            }
            mx0 = fmaxf(mx0, __shfl_xor_sync(0xffffffffu, mx0, 1));
            mx0 = fmaxf(mx0, __shfl_xor_sync(0xffffffffu, mx0, 2));
            mx1 = fmaxf(mx1, __shfl_xor_sync(0xffffffffu, mx1, 1));
            mx1 = fmaxf(mx1, __shfl_xor_sync(0xffffffffu, mx1, 2));
            const float mn0 = fmaxf(m_old0, mx0);
            const float mn1 = fmaxf(m_old1, mx1);
            float s0 = 0.f, s1 = 0.f;
            #pragma unroll
            for (int j = 0; j < 8; j++) {
                float p00 = __expf(acc_s[j][0] - mn0);
                float p01 = __expf(acc_s[j][1] - mn0);
                float p10 = __expf(acc_s[j][2] - mn1);
                float p11 = __expf(acc_s[j][3] - mn1);
                s0 += p00 + p01; s1 += p10 + p11;
                sPh[r0 * 36 + 4 * j + tg] = h2u(__floats2half2_rn(p00, p01));
                sPh[r1 * 36 + 4 * j + tg] = h2u(__floats2half2_rn(p10, p11));
            }
            s0 += __shfl_xor_sync(0xffffffffu, s0, 1);
            s0 += __shfl_xor_sync(0xffffffffu, s0, 2);
            s1 += __shfl_xor_sync(0xffffffffu, s1, 1);
            s1 += __shfl_xor_sync(0xffffffffu, s1, 2);
            if (tg == 0) {
                float sc0 = __expf(m_old0 - mn0);
                float sc1 = __expf(m_old1 - mn1);
                rs[r0] = sc0; m_s[r0] = mn0; l_s[r0] = l_s[r0] * sc0 + s0;
                rs[r1] = sc1; m_s[r1] = mn1; l_s[r1] = l_s[r1] * sc1 + s1;
            }
        }
        __syncthreads();   // S3

        // ---- prefetch next KE tile (overlaps PV MMA below) ----
        if (kt < qt) {
            const int k0n = k0 + 64;
            int dlon = q0 - k0n - 63; if (dlon < 0) dlon = 0;
            #pragma unroll
            for (int t = 0; t < 6; t++) {
                int e = tid + t * 256;
                int r = e >> 3, c8 = e & 7;
                const __half* src = (r < 64) ? Kg + (size_t)(k0n + r) * HS + c8 * 8
                                             : Eg + (size_t)(dlon + r - 64) * HS + c8 * 8;
                cpa16(aKE + (r * 36 + c8 * 4) * 4, src);
            }
            cpa_commit();
        }

        // ---- rescale O accumulator, then P @ V (ldmatrix) ----
        {
            const float s0 = rs[wMs * 16 + g];
            const float s1 = rs[wMs * 16 + g + 8];
            #pragma unroll
            for (int j = 0; j < 4; j++) {
                acc_o[j][0] *= s0; acc_o[j][1] *= s0;
                acc_o[j][2] *= s1; acc_o[j][3] *= s1;
            }
            #pragma unroll
            for (int ks = 0; ks < 4; ks++) {
                uint32_t af[4];
                ldsm4(af, aP + ((wMs * 16 + l15) * 72 + ks * 16 + lh) * 2);
                #pragma unroll
                for (int jp = 0; jp < 2; jp++) {
                    int nj = wNs * 32 + jp * 16;
                    uint32_t bq[4];
                    ldsm4t(bq, aV + ((ks * 16 + l15) * 72 + nj + lh) * 2);
                    mma16(acc_o[2*jp],   af, bq);
                    mma16(acc_o[2*jp+1], af, bq + 2);
                }
            }
        }
    }

    // ---- epilogue: divide by l, store fp16 ----
    const int b = bn >> 4, n = bn & 15;
    const float inv0 = 1.f / l_s[wMs * 16 + g];
    const float inv1 = 1.f / l_s[wMs * 16 + g + 8];
    #pragma unroll
    for (int j = 0; j < 4; j++) {
        #pragma unroll
        for (int cr = 0; cr < 4; cr++) {
            int q = q0 + wMs * 16 + g + (cr >> 1) * 8;
            int h = wNs * 32 + j * 8 + tg * 2 + (cr & 1);
            g_Oh[(((size_t)b * SEQ + q) * NHEAD + n) * HS + h] =
                __float2half_rn(acc_o[j][cr] * ((cr >> 1) ? inv1 : inv0));
        }
    }
}

// ---------------- 4) out = O @ (out_kernel * scale) + bias, ldmatrix --------
__global__ __launch_bounds__(256) void proj_kernel(
    const float* __restrict__ bias, float* __restrict__ out)
{
    __shared__ __align__(16) __half sA[128 * 72];
    __shared__ __align__(16) __half sB[64 * 136];
    const int tid = threadIdx.x, lane = tid & 31, wid = tid >> 5;
    const int g = lane >> 2, tg = lane & 3;
    const int warpN = wid & 1, warpM = wid >> 1;
    const int m0 = blockIdx.y * 128, n0 = blockIdx.x * 128;
    const uint32_t aA = (uint32_t)__cvta_generic_to_shared(sA);
    const uint32_t aB = (uint32_t)__cvta_generic_to_shared(sB);
    const int l15 = lane & 15, lh = (lane & 16) >> 1;

    float acc[2][8][4] = {};
    for (int k0 = 0; k0 < DM; k0 += 64) {
        #pragma unroll
        for (int t = 0; t < 4; t++) {
            int e = tid + t * 256;
            int r = e >> 3, c = (e & 7) * 8;
            *(uint4*)&sA[r * 72 + c] = *(const uint4*)&g_Oh[(size_t)(m0 + r) * DM + k0 + c];
        }
        #pragma unroll
        for (int t = 0; t < 4; t++) {
            int e = tid + t * 256;
            int r = e >> 4, c = (e & 15) * 8;
            *(uint4*)&sB[r * 136 + c] = *(const uint4*)&g_wkh[(size_t)(k0 + r) * DM + n0 + c];
        }
        __syncthreads();
        #pragma unroll
        for (int ks = 0; ks < 4; ks++) {
            uint32_t af[2][4];
            #pragma unroll
            for (int i = 0; i < 2; i++) {
                int mr = warpM * 32 + i * 16;
                ldsm4(af[i], aA + ((mr + l15) * 72 + ks * 16 + lh) * 2);
            }
            #pragma unroll
            for (int jp = 0; jp < 4; jp++) {
                int nj = warpN * 64 + jp * 16;
                uint32_t bq[4];
                ldsm4t(bq, aB + ((ks * 16 + l15) * 136 + nj + lh) * 2);
                mma16(acc[0][2*jp],   af[0], bq);
                mma16(acc[0][2*jp+1], af[0], bq + 2);
                mma16(acc[1][2*jp],   af[1], bq);
                mma16(acc[1][2*jp+1], af[1], bq + 2);
            }
        }
        __syncthreads();
    }

    const float okscale = 0.03125f;   // (1024*1024)^-0.25
    #pragma unroll
    for (int i = 0; i < 2; i++) {
        #pragma unroll
        for (int j = 0; j < 8; j++) {
            #pragma unroll
            for (int cr = 0; cr < 4; cr++) {
                int m = m0 + warpM * 32 + i * 16 + g + (cr >> 1) * 8;
                int c = n0 + warpN * 64 + j * 8 + tg * 2 + (cr & 1);
                out[(size_t)m * DM + c] = acc[i][j][cr] * okscale + bias[c];
            }
        }
    }
}

// ---------------- launcher ---------------------------------------------------
extern "C" void kernel_launch(void* const* d_in, const int* in_sizes, int n_in,
                              void* d_out, int out_size)
{
    const float* inp = (const float*)d_in[0];   // (2, 2048, 1024)
    const float* qkv = (const float*)d_in[1];   // (1024, 3, 16, 64)
    const float* qb  = (const float*)d_in[2];   // (16, 64)
    const float* pos = (const float*)d_in[3];   // (256, 16, 64)
    const float* wk  = (const float*)d_in[4];   // (1024, 1024)
    const float* ob  = (const float*)d_in[5];   // (1024,)
    float* out = (float*)d_out;                 // (2, 2048, 1024)

    const int AT_SMEM = 18624 * 4;   // 74496 B -> 2 blocks/SM
    cudaFuncSetAttribute(attn_kernel,
                         cudaFuncAttributeMaxDynamicSharedMemorySize, AT_SMEM);

    __half *d_inph, *d_wh, *d_wkh;
    cudaGetSymbolAddress((void**)&d_inph, g_inph);
    cudaGetSymbolAddress((void**)&d_wh,   g_wh);
    cudaGetSymbolAddress((void**)&d_wkh,  g_wkh);

    cvt_kernel<<<(BATCH*SEQ*DM/4 + 255)/256, 256>>>((const float4*)inp, (uint2*)d_inph, BATCH*SEQ*DM/4);
    cvt_kernel<<<(DM*BN3/4 + 255)/256, 256>>>((const float4*)qkv, (uint2*)d_wh, DM*BN3/4);
    cvt_kernel<<<(DM*DM/4 + 255)/256, 256>>>((const float4*)wk, (uint2*)d_wkh, DM*DM/4);

    qkv_kernel<<<dim3(BN3 / 128, (BATCH * SEQ) / 128), 256>>>(qb);
    emb_kernel<<<SEQ, 256>>>(pos);
    attn_kernel<<<dim3(SEQ / 64, BATCH * NHEAD), 256, AT_SMEM>>>();
    proj_kernel<<<dim3(DM / 128, (BATCH * SEQ) / 128), 256>>>(ob, out);
}